// round 5
// baseline (speedup 1.0000x reference)
#include <cuda_runtime.h>
#include <cuda_bf16.h>
#include <cstdint>

// ---------------------------------------------------------------------------
// TR_Linear via two bf16-split GEMMs on the tensor pipe (portable PTX:
// mma.sync.m16n8k16.bf16 / ldmatrix / cp.async).
//   Pp^T[n][i'] (1024x1024), n=(r2*16+r4)*4+h ;  C1 = x @ Pp  (K=1024)
//   Q2^T[n2][k] (1024x256),  k=r2*16+r4, n2=i0*32+i1
//   y[b, n2*4+h] = sum_k C1[b,k*4+h]*Q2[k,n2] + bias
// Precision: v = hi + lo (bf16); D += Ahi*Bhi + Ahi*Blo + Alo*Bhi (fp32 acc)
// R5: 512-thread blocks (4 warps/SMSP), gemm1 256x128 tile 3-stage ring,
// gemm2 128b x 64n2 x 4h with resident Q2 and 16 k16-chunks.
// ---------------------------------------------------------------------------

#define MTOT 8192
#define PAD 40   // bf16 elems per 32-elem k-row (80B = 5x16B -> conflict-free)

typedef __nv_bfloat16 bf16;

__device__ bf16 g_xh[MTOT * 1024];
__device__ bf16 g_xl[MTOT * 1024];
__device__ bf16 g_pph[1024 * 1024];
__device__ bf16 g_ppl[1024 * 1024];
__device__ bf16 g_q2h[1024 * 256];
__device__ bf16 g_q2l[1024 * 256];
__device__ bf16 g_c1h[4 * MTOT * 256];   // [h][b][k2]
__device__ bf16 g_c1l[4 * MTOT * 256];

// ========================= PTX helpers (portable) ==========================
__device__ __forceinline__ void cp16(uint32_t dst, const void* src) {
    asm volatile("cp.async.cg.shared.global [%0], [%1], 16;" :: "r"(dst), "l"(src));
}
#define CP_COMMIT() asm volatile("cp.async.commit_group;" ::: "memory")
#define CP_WAIT(N)  asm volatile("cp.async.wait_group %0;" :: "n"(N) : "memory")

__device__ __forceinline__ void ldm4(uint32_t& r0, uint32_t& r1, uint32_t& r2, uint32_t& r3,
                                     uint32_t addr) {
    asm volatile("ldmatrix.sync.aligned.m8n8.x4.shared.b16 {%0,%1,%2,%3}, [%4];"
                 : "=r"(r0), "=r"(r1), "=r"(r2), "=r"(r3) : "r"(addr));
}
__device__ __forceinline__ void mma_bf16(float* d, const uint32_t* a, const uint32_t* b) {
    asm volatile("mma.sync.aligned.m16n8k16.row.col.f32.bf16.bf16.f32 "
                 "{%0,%1,%2,%3}, {%4,%5,%6,%7}, {%8,%9}, {%0,%1,%2,%3};"
                 : "+f"(d[0]), "+f"(d[1]), "+f"(d[2]), "+f"(d[3])
                 : "r"(a[0]), "r"(a[1]), "r"(a[2]), "r"(a[3]), "r"(b[0]), "r"(b[1]));
}
__device__ __forceinline__ uint32_t cvta_s(const void* p) {
    return (uint32_t)__cvta_generic_to_shared(p);
}
__device__ __forceinline__ void split2(float v, bf16& h, bf16& l) {
    h = __float2bfloat16_rn(v);
    l = __float2bfloat16_rn(v - __bfloat162float(h));
}

// ========================= prepass kernels =================================
__global__ void conv_x_kernel(const float* __restrict__ x) {
    int i = blockIdx.x * blockDim.x + threadIdx.x;
    bf16 h, l;
    split2(x[i], h, l);
    g_xh[i] = h;
    g_xl[i] = l;
}

__global__ void build_pp_kernel(const float* __restrict__ c2, const float* __restrict__ c3) {
    int idx = blockIdx.x * blockDim.x + threadIdx.x;   // n*1024 + i'
    int n = idx >> 10, ip = idx & 1023;
    int r2 = n >> 6, r4 = (n >> 2) & 15, h = n & 3;
    int o0 = h * 16 + (ip >> 6), o1 = ip & 63;
    const float* a = c2 + (r2 * 64 + o0) * 16;
    float s = 0.f;
#pragma unroll
    for (int r3 = 0; r3 < 16; r3++) s += a[r3] * c3[(r3 * 64 + o1) * 16 + r4];
    bf16 hh, ll;
    split2(s, hh, ll);
    g_pph[idx] = hh;
    g_ppl[idx] = ll;
}

__global__ void build_q2_kernel(const float* __restrict__ c0, const float* __restrict__ c1) {
    int idx = blockIdx.x * blockDim.x + threadIdx.x;   // n2*256 + k
    int n2 = idx >> 8, k = idx & 255;
    int r2 = k >> 4, r4 = k & 15;
    int i0 = n2 >> 5, i1 = n2 & 31;
    const float* a = c0 + (r4 * 32 + i0) * 16;
    float s = 0.f;
#pragma unroll
    for (int r1 = 0; r1 < 16; r1++) s += a[r1] * c1[(r1 * 32 + i1) * 16 + r2];
    bf16 hh, ll;
    split2(s, hh, ll);
    g_q2h[idx] = hh;
    g_q2l[idx] = ll;
}

// ========================= GEMM1: C1 = x @ Pp ==============================
// 256x128 block tile, 512 threads (16 warps, warp tile 64x32).
// K=1024 in 32 chunks of 32. 3-stage cp.async ring.
// Stage layout (bf16): Ah[256][PAD] @0, Al @256*PAD, Bh[128][PAD] @512*PAD, Bl.
#define G1_ASTRIDE (256 * PAD)
#define G1_BOFF    (512 * PAD)
#define G1_BSTRIDE (128 * PAD)
#define G1_SLOT    (768 * PAD)             // 30720 bf16 = 61440 B
#define G1_STAGES  3
#define G1_SMEM    (G1_STAGES * G1_SLOT * 2)   // 184320 B

__global__ __launch_bounds__(512, 1) void gemm1_mma() {
    extern __shared__ char dsm[];
    bf16* sm = (bf16*)dsm;
    const int t = threadIdx.x, wid = t >> 5, lane = t & 31;
    const int bm = blockIdx.y * 256, bn = blockIdx.x * 128;
    const int wm = wid & 3, wn = wid >> 2;     // warp tile 64m x 32n

    float acc[4][4][4];
#pragma unroll
    for (int a = 0; a < 4; a++)
#pragma unroll
        for (int b = 0; b < 4; b++)
#pragma unroll
            for (int c = 0; c < 4; c++) acc[a][b][c] = 0.f;

    auto load_stage = [&](int s, int k0) {
#pragma unroll
        for (int i = 0; i < 6; i++) {
            int gi = i * 512 + t;
            if (gi < 2048) {                  // A: 2 planes x 256 rows x 4 chunks
                int plane = gi >> 10, rem = gi & 1023, row = rem >> 2, c = rem & 3;
                const bf16* src = (plane ? g_xl : g_xh) +
                    (size_t)(bm + row) * 1024 + k0 + c * 8;
                cp16(cvta_s(sm + s * G1_SLOT + plane * G1_ASTRIDE + row * PAD + c * 8), src);
            } else {                          // B: 2 planes x 128 rows x 4 chunks
                int b = gi - 2048;
                int plane = b >> 9, rem = b & 511, row = rem >> 2, c = rem & 3;
                const bf16* src = (plane ? g_ppl : g_pph) +
                    (size_t)(bn + row) * 1024 + k0 + c * 8;
                cp16(cvta_s(sm + s * G1_SLOT + G1_BOFF + plane * G1_BSTRIDE + row * PAD + c * 8), src);
            }
        }
    };

    const int lr = lane & 15, lc = lane >> 4;

    auto compute = [&](int s) {
        uint32_t abase = cvta_s(sm) + (uint32_t)(s * G1_SLOT) * 2;
#pragma unroll
        for (int kk = 0; kk < 2; kk++) {
            uint32_t koff = (uint32_t)((kk * 2 + lc) * 8) * 2;
            uint32_t ah[4][4], al[4][4], bh[4][2], bl[4][2];
#pragma unroll
            for (int mi = 0; mi < 4; mi++) {
                uint32_t off = (uint32_t)((wm * 64 + mi * 16 + lr) * PAD) * 2 + koff;
                ldm4(ah[mi][0], ah[mi][1], ah[mi][2], ah[mi][3], abase + off);
                ldm4(al[mi][0], al[mi][1], al[mi][2], al[mi][3],
                     abase + G1_ASTRIDE * 2 + off);
            }
#pragma unroll
            for (int p = 0; p < 2; p++) {
                uint32_t off = (uint32_t)((wn * 32 + p * 16 + lr) * PAD) * 2 + koff;
                uint32_t r0, r1, r2, r3;
                ldm4(r0, r1, r2, r3, abase + G1_BOFF * 2 + off);
                bh[2 * p][0] = r0; bh[2 * p][1] = r2;
                bh[2 * p + 1][0] = r1; bh[2 * p + 1][1] = r3;
                ldm4(r0, r1, r2, r3, abase + (G1_BOFF + G1_BSTRIDE) * 2 + off);
                bl[2 * p][0] = r0; bl[2 * p][1] = r2;
                bl[2 * p + 1][0] = r1; bl[2 * p + 1][1] = r3;
            }
#pragma unroll
            for (int mi = 0; mi < 4; mi++)
#pragma unroll
                for (int ni = 0; ni < 4; ni++) {
                    mma_bf16(acc[mi][ni], ah[mi], bh[ni]);
                    mma_bf16(acc[mi][ni], al[mi], bh[ni]);
                    mma_bf16(acc[mi][ni], ah[mi], bl[ni]);
                }
        }
    };

    load_stage(0, 0);
    CP_COMMIT();
    load_stage(1, 32);
    CP_COMMIT();
    for (int kc = 0; kc < 32; kc++) {
        CP_WAIT(1);
        __syncthreads();
        compute(kc % 3);
        if (kc + 2 < 32) load_stage((kc + 2) % 3, (kc + 2) * 32);
        CP_COMMIT();
    }

    // ---- epilogue: stage fp32 tile, then bf16-split into C1[h][b][k2] ----
    CP_WAIT(0);
    __syncthreads();
    float* stg = (float*)dsm;     // [256][132]
#pragma unroll
    for (int mi = 0; mi < 4; mi++)
#pragma unroll
        for (int ni = 0; ni < 4; ni++) {
            int r = wm * 64 + mi * 16 + (lane >> 2);
            int c = wn * 32 + ni * 8 + (lane & 3) * 2;
            stg[r * 132 + c]           = acc[mi][ni][0];
            stg[r * 132 + c + 1]       = acc[mi][ni][1];
            stg[(r + 8) * 132 + c]     = acc[mi][ni][2];
            stg[(r + 8) * 132 + c + 1] = acc[mi][ni][3];
        }
    __syncthreads();

    const int kb = bn >> 2;
#pragma unroll
    for (int i = 0; i < 16; i++) {
        int g = i * 512 + t;                   // 8192 groups of 4 k2
        int row = g >> 5, rem = g & 31, h = rem >> 3, kg = rem & 7;
        ushort4 vh, vl;
        bf16 hh, ll;
        split2(stg[row * 132 + (kg * 4 + 0) * 4 + h], hh, ll);
        vh.x = __bfloat16_as_ushort(hh); vl.x = __bfloat16_as_ushort(ll);
        split2(stg[row * 132 + (kg * 4 + 1) * 4 + h], hh, ll);
        vh.y = __bfloat16_as_ushort(hh); vl.y = __bfloat16_as_ushort(ll);
        split2(stg[row * 132 + (kg * 4 + 2) * 4 + h], hh, ll);
        vh.z = __bfloat16_as_ushort(hh); vl.z = __bfloat16_as_ushort(ll);
        split2(stg[row * 132 + (kg * 4 + 3) * 4 + h], hh, ll);
        vh.w = __bfloat16_as_ushort(hh); vl.w = __bfloat16_as_ushort(ll);
        size_t o = ((size_t)h * MTOT + bm + row) * 256 + kb + kg * 4;
        *(ushort4*)(g_c1h + o) = vh;
        *(ushort4*)(g_c1l + o) = vl;
    }
}

// ========================= GEMM2: y = C1_h @ Q2^T + bias ===================
// 512 threads, block 128b x 64n2 x 4h. Warp wid: h = wid>>2, rows (wid&3)*32.
// K=256 in 16 chunks of 16 (KPAD=24 -> 48B rows, 3x16B odd -> conflict-free).
// Q2 resident full-K (BPAD=264 -> 528B rows).
#define G2_KPAD 24
#define G2_APLANE (4 * 128 * G2_KPAD)      // 12288 bf16
#define G2_ASLOT  (2 * G2_APLANE)          // 24576 bf16 = 49152 B
#define G2_STAGES 3
#define G2_BOFF   (G2_STAGES * G2_ASLOT)   // 73728 bf16
#define BPAD 264
#define G2_BPLANE (64 * BPAD)              // 16896 bf16
#define G2_SMEM   ((G2_BOFF + 2 * G2_BPLANE) * 2)   // 215040 B

__global__ __launch_bounds__(512, 1) void gemm2_mma(const float* __restrict__ bias,
                                                    float* __restrict__ Y) {
    extern __shared__ char dsm[];
    bf16* sm = (bf16*)dsm;
    const int t = threadIdx.x, wid = t >> 5, lane = t & 31;
    const int bm = blockIdx.y * 128, bn2 = blockIdx.x * 64;
    const int wh = wid >> 2, mh = wid & 3;     // warp: h = wh, rows mh*32..+31

    float acc[2][8][4];
#pragma unroll
    for (int a = 0; a < 2; a++)
#pragma unroll
        for (int b = 0; b < 8; b++)
#pragma unroll
            for (int c = 0; c < 4; c++) acc[a][b][c] = 0.f;

    auto load_B = [&]() {       // full-K Q2, both planes, once
#pragma unroll
        for (int i = 0; i < 8; i++) {
            int gi = i * 512 + t;                    // 4096 x 16B
            int plane = gi >> 11, rem = gi & 2047, row = rem >> 5, c = rem & 31;
            const bf16* src = (plane ? g_q2l : g_q2h) + (size_t)(bn2 + row) * 256 + c * 8;
            cp16(cvta_s(sm + G2_BOFF + plane * G2_BPLANE + row * BPAD + c * 8), src);
        }
    };
    auto load_A = [&](int s, int k0) {
#pragma unroll
        for (int i = 0; i < 4; i++) {
            int gi = i * 512 + t;                    // 2048 x 16B
            int plane = gi >> 10, rem = gi & 1023;
            int h = rem >> 8, rem2 = rem & 255, row = rem2 >> 1, c = rem2 & 1;
            const bf16* src = (plane ? g_c1l : g_c1h) +
                ((size_t)h * MTOT + bm + row) * 256 + k0 + c * 8;
            cp16(cvta_s(sm + s * G2_ASLOT + plane * G2_APLANE + (h * 128 + row) * G2_KPAD + c * 8), src);
        }
    };

    const int lr = lane & 15, lc = lane >> 4;

    auto compute = [&](int s, int kc) {
        uint32_t abase = cvta_s(sm) + (uint32_t)(s * G2_ASLOT) * 2;
        uint32_t bbase = cvta_s(sm) + (uint32_t)G2_BOFF * 2;
        uint32_t koffA = (uint32_t)(lc * 8) * 2;
        uint32_t ah[2][4], al[2][4], bh[8][2], bl[8][2];
#pragma unroll
        for (int mi = 0; mi < 2; mi++) {
            uint32_t off = (uint32_t)((wh * 128 + mh * 32 + mi * 16 + lr) * G2_KPAD) * 2 + koffA;
            ldm4(ah[mi][0], ah[mi][1], ah[mi][2], ah[mi][3], abase + off);
            ldm4(al[mi][0], al[mi][1], al[mi][2], al[mi][3],
                 abase + G2_APLANE * 2 + off);
        }
        uint32_t kb = (uint32_t)(kc * 16 + lc * 8) * 2;
#pragma unroll
        for (int p = 0; p < 4; p++) {
            uint32_t off = (uint32_t)((p * 16 + lr) * BPAD) * 2 + kb;
            uint32_t r0, r1, r2, r3;
            ldm4(r0, r1, r2, r3, bbase + off);
            bh[2 * p][0] = r0; bh[2 * p][1] = r2;
            bh[2 * p + 1][0] = r1; bh[2 * p + 1][1] = r3;
            ldm4(r0, r1, r2, r3, bbase + G2_BPLANE * 2 + off);
            bl[2 * p][0] = r0; bl[2 * p][1] = r2;
            bl[2 * p + 1][0] = r1; bl[2 * p + 1][1] = r3;
        }
#pragma unroll
        for (int mi = 0; mi < 2; mi++)
#pragma unroll
            for (int ni = 0; ni < 8; ni++) {
                mma_bf16(acc[mi][ni], ah[mi], bh[ni]);
                mma_bf16(acc[mi][ni], al[mi], bh[ni]);
                mma_bf16(acc[mi][ni], ah[mi], bl[ni]);
            }
    };

    load_B();
    load_A(0, 0);
    CP_COMMIT();                 // group 0: B + A0
    load_A(1, 16);
    CP_COMMIT();                 // group 1: A1
    for (int kc = 0; kc < 16; kc++) {
        CP_WAIT(1);
        __syncthreads();
        compute(kc % 3, kc);
        if (kc + 2 < 16) load_A((kc + 2) % 3, (kc + 2) * 16);
        CP_COMMIT();
    }

    // ---- epilogue: reorder (h, n2l) -> col n2l*4+h in smem, coalesced out ----
    CP_WAIT(0);
    __syncthreads();
    float* stg = (float*)dsm;     // [128][260]
#pragma unroll
    for (int mi = 0; mi < 2; mi++)
#pragma unroll
        for (int ni = 0; ni < 8; ni++) {
            int r = mh * 32 + mi * 16 + (lane >> 2);
            int n2l = ni * 8 + (lane & 3) * 2;
            stg[r * 260 + n2l * 4 + wh]             = acc[mi][ni][0];
            stg[r * 260 + (n2l + 1) * 4 + wh]       = acc[mi][ni][1];
            stg[(r + 8) * 260 + n2l * 4 + wh]       = acc[mi][ni][2];
            stg[(r + 8) * 260 + (n2l + 1) * 4 + wh] = acc[mi][ni][3];
        }
    __syncthreads();

#pragma unroll
    for (int i = 0; i < 16; i++) {
        int g = i * 512 + t;                    // 8192 float4 groups
        int r = g >> 6, c4 = (g & 63) * 4;
        float4 v = *(const float4*)&stg[r * 260 + c4];
        float4 bz = *(const float4*)(bias + bn2 * 4 + c4);
        v.x += bz.x; v.y += bz.y; v.z += bz.z; v.w += bz.w;
        *(float4*)(Y + (size_t)(bm + r) * 4096 + bn2 * 4 + c4) = v;
    }
}

// ========================= launch ==========================================
extern "C" void kernel_launch(void* const* d_in, const int* in_sizes, int n_in,
                              void* d_out, int out_size) {
    const float* x     = (const float*)d_in[0];
    const float* core0 = (const float*)d_in[1];
    const float* core1 = (const float*)d_in[2];
    const float* core2 = (const float*)d_in[3];
    const float* core3 = (const float*)d_in[4];
    const float* bias  = (const float*)d_in[5];
    float* y = (float*)d_out;

    cudaFuncSetAttribute(gemm1_mma, cudaFuncAttributeMaxDynamicSharedMemorySize, G1_SMEM);
    cudaFuncSetAttribute(gemm2_mma, cudaFuncAttributeMaxDynamicSharedMemorySize, G2_SMEM);

    conv_x_kernel<<<(MTOT * 1024) / 256, 256>>>(x);
    build_pp_kernel<<<(1024 * 1024) / 256, 256>>>(core2, core3);
    build_q2_kernel<<<(1024 * 256) / 256, 256>>>(core0, core1);

    gemm1_mma<<<dim3(8, 32), 512, G1_SMEM>>>();
    gemm2_mma<<<dim3(16, 64), 512, G2_SMEM>>>(bias, y);
}

// round 6
// speedup vs baseline: 1.2663x; 1.2663x over previous
#include <cuda_runtime.h>
#include <cuda_bf16.h>
#include <cstdint>

// ---------------------------------------------------------------------------
// TR_Linear via two bf16-split GEMMs on the tensor pipe (portable PTX:
// mma.sync.m16n8k16.bf16 / ldmatrix / cp.async).
//   Pp^T[n][i'] (1024x1024), n=(r2*16+r4)*4+h ;  C1 = x @ Pp  (K=1024)
//   Q2^T[n2][k] (1024x256),  k=r2*16+r4, n2=i0*32+i1
//   y[b, n2*4+h] = sum_k C1[b,k*4+h]*Q2[k,n2] + bias
// Precision: v = hi + lo (bf16); D += Ahi*Bhi + Ahi*Blo + Alo*Bhi (fp32 acc)
// R6: 2 CTAs/SM (cross-CTA latency hiding). XOR-swizzled 64B rows
// (conflict-free, no padding) -> gemm1 3-stage ring fits 2 CTAs;
// gemm2 back to k32 chunks, A+B streamed, 2-stage ring, 2 CTAs.
// ---------------------------------------------------------------------------

#define MTOT 8192

typedef __nv_bfloat16 bf16;

__device__ bf16 g_xh[MTOT * 1024];
__device__ bf16 g_xl[MTOT * 1024];
__device__ bf16 g_pph[1024 * 1024];
__device__ bf16 g_ppl[1024 * 1024];
__device__ bf16 g_q2h[1024 * 256];
__device__ bf16 g_q2l[1024 * 256];
__device__ bf16 g_c1h[4 * MTOT * 256];   // [h][b][k2]
__device__ bf16 g_c1l[4 * MTOT * 256];

// ========================= PTX helpers (portable) ==========================
__device__ __forceinline__ void cp16(uint32_t dst, const void* src) {
    asm volatile("cp.async.cg.shared.global [%0], [%1], 16;" :: "r"(dst), "l"(src));
}
#define CP_COMMIT() asm volatile("cp.async.commit_group;" ::: "memory")
#define CP_WAIT(N)  asm volatile("cp.async.wait_group %0;" :: "n"(N) : "memory")

__device__ __forceinline__ void ldm4(uint32_t& r0, uint32_t& r1, uint32_t& r2, uint32_t& r3,
                                     uint32_t addr) {
    asm volatile("ldmatrix.sync.aligned.m8n8.x4.shared.b16 {%0,%1,%2,%3}, [%4];"
                 : "=r"(r0), "=r"(r1), "=r"(r2), "=r"(r3) : "r"(addr));
}
__device__ __forceinline__ void mma_bf16(float* d, const uint32_t* a, const uint32_t* b) {
    asm volatile("mma.sync.aligned.m16n8k16.row.col.f32.bf16.bf16.f32 "
                 "{%0,%1,%2,%3}, {%4,%5,%6,%7}, {%8,%9}, {%0,%1,%2,%3};"
                 : "+f"(d[0]), "+f"(d[1]), "+f"(d[2]), "+f"(d[3])
                 : "r"(a[0]), "r"(a[1]), "r"(a[2]), "r"(a[3]), "r"(b[0]), "r"(b[1]));
}
__device__ __forceinline__ uint32_t cvta_s(const void* p) {
    return (uint32_t)__cvta_generic_to_shared(p);
}
__device__ __forceinline__ void split2(float v, bf16& h, bf16& l) {
    h = __float2bfloat16_rn(v);
    l = __float2bfloat16_rn(v - __bfloat162float(h));
}

// 64B-row swizzle: row stride = 32 bf16 (64B); 16B granule c (0..3) is stored
// at physical granule c ^ ((row>>1)&3).  For ldmatrix (8 rows x 16B) the 8
// physical granules are distinct mod 8 -> conflict-free; same for cp.async.
__device__ __forceinline__ uint32_t swz(int row, int c) {
    return (uint32_t)(row * 32 + ((c ^ ((row >> 1) & 3)) * 8));
}

// ========================= prepass kernels =================================
__global__ void conv_x_kernel(const float* __restrict__ x) {
    int i = blockIdx.x * blockDim.x + threadIdx.x;
    bf16 h, l;
    split2(x[i], h, l);
    g_xh[i] = h;
    g_xl[i] = l;
}

__global__ void build_pp_kernel(const float* __restrict__ c2, const float* __restrict__ c3) {
    int idx = blockIdx.x * blockDim.x + threadIdx.x;   // n*1024 + i'
    int n = idx >> 10, ip = idx & 1023;
    int r2 = n >> 6, r4 = (n >> 2) & 15, h = n & 3;
    int o0 = h * 16 + (ip >> 6), o1 = ip & 63;
    const float* a = c2 + (r2 * 64 + o0) * 16;
    float s = 0.f;
#pragma unroll
    for (int r3 = 0; r3 < 16; r3++) s += a[r3] * c3[(r3 * 64 + o1) * 16 + r4];
    bf16 hh, ll;
    split2(s, hh, ll);
    g_pph[idx] = hh;
    g_ppl[idx] = ll;
}

__global__ void build_q2_kernel(const float* __restrict__ c0, const float* __restrict__ c1) {
    int idx = blockIdx.x * blockDim.x + threadIdx.x;   // n2*256 + k
    int n2 = idx >> 8, k = idx & 255;
    int r2 = k >> 4, r4 = k & 15;
    int i0 = n2 >> 5, i1 = n2 & 31;
    const float* a = c0 + (r4 * 32 + i0) * 16;
    float s = 0.f;
#pragma unroll
    for (int r1 = 0; r1 < 16; r1++) s += a[r1] * c1[(r1 * 32 + i1) * 16 + r2];
    bf16 hh, ll;
    split2(s, hh, ll);
    g_q2h[idx] = hh;
    g_q2l[idx] = ll;
}

// ========================= GEMM1: C1 = x @ Pp ==============================
// 128x128 block tile, 256 threads (8 warps, warp tile 64x32).
// K=1024 in 32 chunks of 32. 3-stage ring, swizzled 64B rows.
// Stage layout (bf16 elems): Ah[128][32] @0, Al @4096, Bh @8192, Bl @12288.
#define G1_SLOT  16384                       // bf16 per stage (32768 B)
#define G1_SMEM  (3 * G1_SLOT * 2)           // 98304 B

__global__ __launch_bounds__(256, 2) void gemm1_mma() {
    extern __shared__ char dsm[];
    bf16* sm = (bf16*)dsm;
    const int t = threadIdx.x, wid = t >> 5, lane = t & 31;
    const int bm = blockIdx.y * 128, bn = blockIdx.x * 128;
    const int wm = wid & 1, wn = wid >> 1;     // warp tile 64m x 32n

    float acc[4][4][4];
#pragma unroll
    for (int a = 0; a < 4; a++)
#pragma unroll
        for (int b = 0; b < 4; b++)
#pragma unroll
            for (int c = 0; c < 4; c++) acc[a][b][c] = 0.f;

    auto load_stage = [&](int s, int k0) {
#pragma unroll
        for (int i = 0; i < 8; i++) {
            int gi = i * 256 + t;                      // 2048 x 16B granules
            int arr = gi >> 9, rem = gi & 511, row = rem >> 2, c = rem & 3;
            const bf16* src;
            if (arr == 0)      src = g_xh  + (size_t)(bm + row) * 1024 + k0 + c * 8;
            else if (arr == 1) src = g_xl  + (size_t)(bm + row) * 1024 + k0 + c * 8;
            else if (arr == 2) src = g_pph + (size_t)(bn + row) * 1024 + k0 + c * 8;
            else               src = g_ppl + (size_t)(bn + row) * 1024 + k0 + c * 8;
            cp16(cvta_s(sm + s * G1_SLOT + arr * 4096 + swz(row, c)), src);
        }
    };

    const int lr = lane & 15, lc = lane >> 4;

    auto compute = [&](int s) {
        uint32_t base = cvta_s(sm) + (uint32_t)(s * G1_SLOT) * 2;
#pragma unroll
        for (int kk = 0; kk < 2; kk++) {
            int kidx = kk * 2 + lc;
            uint32_t ah[4][4], al[4][4], bh[4][2], bl[4][2];
#pragma unroll
            for (int mi = 0; mi < 4; mi++) {
                int row = wm * 64 + mi * 16 + lr;
                uint32_t off = swz(row, kidx) * 2;
                ldm4(ah[mi][0], ah[mi][1], ah[mi][2], ah[mi][3], base + off);
                ldm4(al[mi][0], al[mi][1], al[mi][2], al[mi][3], base + 4096 * 2 + off);
            }
#pragma unroll
            for (int p = 0; p < 2; p++) {
                int row = wn * 32 + p * 16 + lr;
                uint32_t off = swz(row, kidx) * 2;
                uint32_t r0, r1, r2, r3;
                ldm4(r0, r1, r2, r3, base + 8192 * 2 + off);
                bh[2 * p][0] = r0; bh[2 * p][1] = r2;
                bh[2 * p + 1][0] = r1; bh[2 * p + 1][1] = r3;
                ldm4(r0, r1, r2, r3, base + 12288 * 2 + off);
                bl[2 * p][0] = r0; bl[2 * p][1] = r2;
                bl[2 * p + 1][0] = r1; bl[2 * p + 1][1] = r3;
            }
#pragma unroll
            for (int mi = 0; mi < 4; mi++)
#pragma unroll
                for (int ni = 0; ni < 4; ni++) {
                    mma_bf16(acc[mi][ni], ah[mi], bh[ni]);
                    mma_bf16(acc[mi][ni], al[mi], bh[ni]);
                    mma_bf16(acc[mi][ni], ah[mi], bl[ni]);
                }
        }
    };

    load_stage(0, 0);
    CP_COMMIT();
    load_stage(1, 32);
    CP_COMMIT();
    for (int kc = 0; kc < 32; kc++) {
        CP_WAIT(1);
        __syncthreads();
        compute(kc % 3);
        if (kc + 2 < 32) load_stage((kc + 2) % 3, (kc + 2) * 32);
        CP_COMMIT();
    }

    // ---- epilogue: stage fp32 tile, then bf16-split into C1[h][b][k2] ----
    CP_WAIT(0);
    __syncthreads();
    float* stg = (float*)dsm;     // [128][132] = 67584 B <= 98304
#pragma unroll
    for (int mi = 0; mi < 4; mi++)
#pragma unroll
        for (int ni = 0; ni < 4; ni++) {
            int r = wm * 64 + mi * 16 + (lane >> 2);
            int c = wn * 32 + ni * 8 + (lane & 3) * 2;
            stg[r * 132 + c]           = acc[mi][ni][0];
            stg[r * 132 + c + 1]       = acc[mi][ni][1];
            stg[(r + 8) * 132 + c]     = acc[mi][ni][2];
            stg[(r + 8) * 132 + c + 1] = acc[mi][ni][3];
        }
    __syncthreads();

    const int kb = bn >> 2;
#pragma unroll
    for (int i = 0; i < 16; i++) {
        int g = i * 256 + t;                   // 4096 groups of 4 k2
        int row = g >> 5, rem = g & 31, h = rem >> 3, kg = rem & 7;
        ushort4 vh, vl;
        bf16 hh, ll;
        split2(stg[row * 132 + (kg * 4 + 0) * 4 + h], hh, ll);
        vh.x = __bfloat16_as_ushort(hh); vl.x = __bfloat16_as_ushort(ll);
        split2(stg[row * 132 + (kg * 4 + 1) * 4 + h], hh, ll);
        vh.y = __bfloat16_as_ushort(hh); vl.y = __bfloat16_as_ushort(ll);
        split2(stg[row * 132 + (kg * 4 + 2) * 4 + h], hh, ll);
        vh.z = __bfloat16_as_ushort(hh); vl.z = __bfloat16_as_ushort(ll);
        split2(stg[row * 132 + (kg * 4 + 3) * 4 + h], hh, ll);
        vh.w = __bfloat16_as_ushort(hh); vl.w = __bfloat16_as_ushort(ll);
        size_t o = ((size_t)h * MTOT + bm + row) * 256 + kb + kg * 4;
        *(ushort4*)(g_c1h + o) = vh;
        *(ushort4*)(g_c1l + o) = vl;
    }
}

// ========================= GEMM2: y = C1_h @ Q2^T + bias ===================
// 256 threads, block 64b x 64n2 x 4h. Warp: h = wid>>1, rows (wid&1)*32.
// K=256 in 8 chunks of 32. 2-stage ring, A and B both streamed, swizzled rows.
// Stage (bf16): A[pl][h][64][32] @0 (16384), B[pl][64][32] @16384 (4096).
#define G2_SLOT  20480                      // bf16 per stage (40960 B)
#define G2_SMEM  (2 * G2_SLOT * 2)          // 81920 B

__global__ __launch_bounds__(256, 2) void gemm2_mma(const float* __restrict__ bias,
                                                    float* __restrict__ Y) {
    extern __shared__ char dsm[];
    bf16* sm = (bf16*)dsm;
    const int t = threadIdx.x, wid = t >> 5, lane = t & 31;
    const int bm = blockIdx.y * 64, bn2 = blockIdx.x * 64;
    const int wh = wid >> 1, mh = wid & 1;     // warp: h = wh, rows mh*32..+31

    float acc[2][8][4];
#pragma unroll
    for (int a = 0; a < 2; a++)
#pragma unroll
        for (int b = 0; b < 8; b++)
#pragma unroll
            for (int c = 0; c < 4; c++) acc[a][b][c] = 0.f;

    auto load_stage = [&](int s, int k0) {
#pragma unroll
        for (int i = 0; i < 10; i++) {
            int gi = i * 256 + t;
            if (gi < 2048) {                  // A: 2pl x 4h x 64 rows x 4 granules
                int pl = gi >> 10, rem = gi & 1023;
                int h = rem >> 8, r2 = rem & 255, row = r2 >> 2, c = r2 & 3;
                const bf16* src = (pl ? g_c1l : g_c1h) +
                    ((size_t)h * MTOT + bm + row) * 256 + k0 + c * 8;
                cp16(cvta_s(sm + s * G2_SLOT + pl * 8192 + h * 2048 + swz(row, c)), src);
            } else {                          // B: 2pl x 64 rows x 4 granules
                int b = gi - 2048;
                int pl = b >> 8, rem = b & 255, row = rem >> 2, c = rem & 3;
                const bf16* src = (pl ? g_q2l : g_q2h) +
                    (size_t)(bn2 + row) * 256 + k0 + c * 8;
                cp16(cvta_s(sm + s * G2_SLOT + 16384 + pl * 2048 + swz(row, c)), src);
            }
        }
    };

    const int lr = lane & 15, lc = lane >> 4;

    auto compute = [&](int s) {
        uint32_t base = cvta_s(sm) + (uint32_t)(s * G2_SLOT) * 2;
#pragma unroll
        for (int kk = 0; kk < 2; kk++) {
            int kidx = kk * 2 + lc;
            uint32_t ah[2][4], al[2][4], bh[8][2], bl[8][2];
#pragma unroll
            for (int mi = 0; mi < 2; mi++) {
                int row = mh * 32 + mi * 16 + lr;
                uint32_t off = ((uint32_t)(wh * 2048) + swz(row, kidx)) * 2;
                ldm4(ah[mi][0], ah[mi][1], ah[mi][2], ah[mi][3], base + off);
                ldm4(al[mi][0], al[mi][1], al[mi][2], al[mi][3], base + 8192 * 2 + off);
            }
#pragma unroll
            for (int p = 0; p < 4; p++) {
                int row = p * 16 + lr;
                uint32_t off = swz(row, kidx) * 2;
                uint32_t r0, r1, r2, r3;
                ldm4(r0, r1, r2, r3, base + 16384 * 2 + off);
                bh[2 * p][0] = r0; bh[2 * p][1] = r2;
                bh[2 * p + 1][0] = r1; bh[2 * p + 1][1] = r3;
                ldm4(r0, r1, r2, r3, base + 18432 * 2 + off);
                bl[2 * p][0] = r0; bl[2 * p][1] = r2;
                bl[2 * p + 1][0] = r1; bl[2 * p + 1][1] = r3;
            }
#pragma unroll
            for (int mi = 0; mi < 2; mi++)
#pragma unroll
                for (int ni = 0; ni < 8; ni++) {
                    mma_bf16(acc[mi][ni], ah[mi], bh[ni]);
                    mma_bf16(acc[mi][ni], al[mi], bh[ni]);
                    mma_bf16(acc[mi][ni], ah[mi], bl[ni]);
                }
        }
    };

    load_stage(0, 0);
    CP_COMMIT();
    for (int kc = 0; kc < 8; kc++) {
        if (kc + 1 < 8) {
            load_stage((kc + 1) & 1, (kc + 1) * 32);
            CP_COMMIT();
            CP_WAIT(1);
        } else {
            CP_WAIT(0);
        }
        __syncthreads();
        compute(kc & 1);
        __syncthreads();
    }

    // ---- epilogue: reorder (h, n2l) -> col n2l*4+h in smem, coalesced out ----
    float* stg = (float*)dsm;     // [64][260] = 66560 B <= 81920
#pragma unroll
    for (int mi = 0; mi < 2; mi++)
#pragma unroll
        for (int ni = 0; ni < 8; ni++) {
            int r = mh * 32 + mi * 16 + (lane >> 2);
            int n2l = ni * 8 + (lane & 3) * 2;
            stg[r * 260 + n2l * 4 + wh]             = acc[mi][ni][0];
            stg[r * 260 + (n2l + 1) * 4 + wh]       = acc[mi][ni][1];
            stg[(r + 8) * 260 + n2l * 4 + wh]       = acc[mi][ni][2];
            stg[(r + 8) * 260 + (n2l + 1) * 4 + wh] = acc[mi][ni][3];
        }
    __syncthreads();

#pragma unroll
    for (int i = 0; i < 16; i++) {
        int g = i * 256 + t;                    // 4096 float4 groups
        int r = g >> 6, c4 = (g & 63) * 4;
        float4 v = *(const float4*)&stg[r * 260 + c4];
        float4 bz = *(const float4*)(bias + bn2 * 4 + c4);
        v.x += bz.x; v.y += bz.y; v.z += bz.z; v.w += bz.w;
        *(float4*)(Y + (size_t)(bm + r) * 4096 + bn2 * 4 + c4) = v;
    }
}

// ========================= launch ==========================================
extern "C" void kernel_launch(void* const* d_in, const int* in_sizes, int n_in,
                              void* d_out, int out_size) {
    const float* x     = (const float*)d_in[0];
    const float* core0 = (const float*)d_in[1];
    const float* core1 = (const float*)d_in[2];
    const float* core2 = (const float*)d_in[3];
    const float* core3 = (const float*)d_in[4];
    const float* bias  = (const float*)d_in[5];
    float* y = (float*)d_out;

    cudaFuncSetAttribute(gemm1_mma, cudaFuncAttributeMaxDynamicSharedMemorySize, G1_SMEM);
    cudaFuncSetAttribute(gemm2_mma, cudaFuncAttributeMaxDynamicSharedMemorySize, G2_SMEM);

    conv_x_kernel<<<(MTOT * 1024) / 256, 256>>>(x);
    build_pp_kernel<<<(1024 * 1024) / 256, 256>>>(core2, core3);
    build_q2_kernel<<<(1024 * 256) / 256, 256>>>(core0, core1);

    gemm1_mma<<<dim3(8, 64), 256, G1_SMEM>>>();
    gemm2_mma<<<dim3(16, 128), 256, G2_SMEM>>>(bias, y);
}

// round 7
// speedup vs baseline: 1.2956x; 1.0232x over previous
#include <cuda_runtime.h>
#include <cuda_bf16.h>
#include <cstdint>

// ---------------------------------------------------------------------------
// TR_Linear via two bf16-split GEMMs on the tensor pipe (portable PTX:
// mma.sync.m16n8k16.bf16 / ldmatrix / cp.async).
//   Pp^T[n][i'] (1024x1024), n=(r2*16+r4)*4+h ;  C1 = x @ Pp  (K=1024)
//   Q2^T[n2][k] (1024x256),  k=r2*16+r4, n2=i0*32+i1
//   y[b, n2*4+h] = sum_k C1[b,k*4+h]*Q2[k,n2] + bias
// Precision: v = hi + lo (bf16); D += Ahi*Bhi + Ahi*Blo + Alo*Bhi (fp32 acc)
// R7: gemm1 loads issued before MMA burst; gemm2 rebuilt as bm32 x n2-64 x 4h
// with resident Q2-hi, 3-stage (A+Q2lo) ring, single sync per chunk, 2 CTAs/SM.
// ---------------------------------------------------------------------------

#define MTOT 8192

typedef __nv_bfloat16 bf16;

__device__ bf16 g_xh[MTOT * 1024];
__device__ bf16 g_xl[MTOT * 1024];
__device__ bf16 g_pph[1024 * 1024];
__device__ bf16 g_ppl[1024 * 1024];
__device__ bf16 g_q2h[1024 * 256];
__device__ bf16 g_q2l[1024 * 256];
__device__ bf16 g_c1h[4 * MTOT * 256];   // [h][b][k2]
__device__ bf16 g_c1l[4 * MTOT * 256];

// ========================= PTX helpers (portable) ==========================
__device__ __forceinline__ void cp16(uint32_t dst, const void* src) {
    asm volatile("cp.async.cg.shared.global [%0], [%1], 16;" :: "r"(dst), "l"(src));
}
#define CP_COMMIT() asm volatile("cp.async.commit_group;" ::: "memory")
#define CP_WAIT(N)  asm volatile("cp.async.wait_group %0;" :: "n"(N) : "memory")

__device__ __forceinline__ void ldm4(uint32_t& r0, uint32_t& r1, uint32_t& r2, uint32_t& r3,
                                     uint32_t addr) {
    asm volatile("ldmatrix.sync.aligned.m8n8.x4.shared.b16 {%0,%1,%2,%3}, [%4];"
                 : "=r"(r0), "=r"(r1), "=r"(r2), "=r"(r3) : "r"(addr));
}
__device__ __forceinline__ void mma_bf16(float* d, const uint32_t* a, const uint32_t* b) {
    asm volatile("mma.sync.aligned.m16n8k16.row.col.f32.bf16.bf16.f32 "
                 "{%0,%1,%2,%3}, {%4,%5,%6,%7}, {%8,%9}, {%0,%1,%2,%3};"
                 : "+f"(d[0]), "+f"(d[1]), "+f"(d[2]), "+f"(d[3])
                 : "r"(a[0]), "r"(a[1]), "r"(a[2]), "r"(a[3]), "r"(b[0]), "r"(b[1]));
}
__device__ __forceinline__ uint32_t cvta_s(const void* p) {
    return (uint32_t)__cvta_generic_to_shared(p);
}
__device__ __forceinline__ void split2(float v, bf16& h, bf16& l) {
    h = __float2bfloat16_rn(v);
    l = __float2bfloat16_rn(v - __bfloat162float(h));
}

// 64B-row swizzle: row stride = 32 bf16 (64B); 16B granule c (0..3) stored at
// physical granule c ^ ((row>>1)&3). Conflict-free for ldmatrix + cp.async.
__device__ __forceinline__ uint32_t swz(int row, int c) {
    return (uint32_t)(row * 32 + ((c ^ ((row >> 1) & 3)) * 8));
}

// ========================= prepass kernels =================================
__global__ void conv_x_kernel(const float* __restrict__ x) {
    int i = (blockIdx.x * blockDim.x + threadIdx.x) * 8;
    float4 v0 = *(const float4*)(x + i);
    float4 v1 = *(const float4*)(x + i + 4);
    ushort4 h0, h1, l0, l1;
    bf16 hh, ll;
    split2(v0.x, hh, ll); h0.x = __bfloat16_as_ushort(hh); l0.x = __bfloat16_as_ushort(ll);
    split2(v0.y, hh, ll); h0.y = __bfloat16_as_ushort(hh); l0.y = __bfloat16_as_ushort(ll);
    split2(v0.z, hh, ll); h0.z = __bfloat16_as_ushort(hh); l0.z = __bfloat16_as_ushort(ll);
    split2(v0.w, hh, ll); h0.w = __bfloat16_as_ushort(hh); l0.w = __bfloat16_as_ushort(ll);
    split2(v1.x, hh, ll); h1.x = __bfloat16_as_ushort(hh); l1.x = __bfloat16_as_ushort(ll);
    split2(v1.y, hh, ll); h1.y = __bfloat16_as_ushort(hh); l1.y = __bfloat16_as_ushort(ll);
    split2(v1.z, hh, ll); h1.z = __bfloat16_as_ushort(hh); l1.z = __bfloat16_as_ushort(ll);
    split2(v1.w, hh, ll); h1.w = __bfloat16_as_ushort(hh); l1.w = __bfloat16_as_ushort(ll);
    *(ushort4*)(g_xh + i)     = h0;
    *(ushort4*)(g_xh + i + 4) = h1;
    *(ushort4*)(g_xl + i)     = l0;
    *(ushort4*)(g_xl + i + 4) = l1;
}

__global__ void build_pp_kernel(const float* __restrict__ c2, const float* __restrict__ c3) {
    int idx = blockIdx.x * blockDim.x + threadIdx.x;   // n*1024 + i'
    int n = idx >> 10, ip = idx & 1023;
    int r2 = n >> 6, r4 = (n >> 2) & 15, h = n & 3;
    int o0 = h * 16 + (ip >> 6), o1 = ip & 63;
    const float* a = c2 + (r2 * 64 + o0) * 16;
    float s = 0.f;
#pragma unroll
    for (int r3 = 0; r3 < 16; r3++) s += a[r3] * c3[(r3 * 64 + o1) * 16 + r4];
    bf16 hh, ll;
    split2(s, hh, ll);
    g_pph[idx] = hh;
    g_ppl[idx] = ll;
}

__global__ void build_q2_kernel(const float* __restrict__ c0, const float* __restrict__ c1) {
    int idx = blockIdx.x * blockDim.x + threadIdx.x;   // n2*256 + k
    int n2 = idx >> 8, k = idx & 255;
    int r2 = k >> 4, r4 = k & 15;
    int i0 = n2 >> 5, i1 = n2 & 31;
    const float* a = c0 + (r4 * 32 + i0) * 16;
    float s = 0.f;
#pragma unroll
    for (int r1 = 0; r1 < 16; r1++) s += a[r1] * c1[(r1 * 32 + i1) * 16 + r2];
    bf16 hh, ll;
    split2(s, hh, ll);
    g_q2h[idx] = hh;
    g_q2l[idx] = ll;
}

// ========================= GEMM1: C1 = x @ Pp ==============================
// 128x128 block tile, 256 threads (8 warps, warp tile 64x32).
// K=1024 in 32 chunks of 32. 3-stage ring, swizzled 64B rows.
// Stage layout (bf16 elems): Ah[128][32] @0, Al @4096, Bh @8192, Bl @12288.
#define G1_SLOT  16384                       // bf16 per stage (32768 B)
#define G1_SMEM  (3 * G1_SLOT * 2)           // 98304 B

__global__ __launch_bounds__(256, 2) void gemm1_mma() {
    extern __shared__ char dsm[];
    bf16* sm = (bf16*)dsm;
    const int t = threadIdx.x, wid = t >> 5, lane = t & 31;
    const int bm = blockIdx.y * 128, bn = blockIdx.x * 128;
    const int wm = wid & 1, wn = wid >> 1;     // warp tile 64m x 32n

    float acc[4][4][4];
#pragma unroll
    for (int a = 0; a < 4; a++)
#pragma unroll
        for (int b = 0; b < 4; b++)
#pragma unroll
            for (int c = 0; c < 4; c++) acc[a][b][c] = 0.f;

    auto load_stage = [&](int s, int k0) {
#pragma unroll
        for (int i = 0; i < 8; i++) {
            int gi = i * 256 + t;                      // 2048 x 16B granules
            int arr = gi >> 9, rem = gi & 511, row = rem >> 2, c = rem & 3;
            const bf16* src;
            if (arr == 0)      src = g_xh  + (size_t)(bm + row) * 1024 + k0 + c * 8;
            else if (arr == 1) src = g_xl  + (size_t)(bm + row) * 1024 + k0 + c * 8;
            else if (arr == 2) src = g_pph + (size_t)(bn + row) * 1024 + k0 + c * 8;
            else               src = g_ppl + (size_t)(bn + row) * 1024 + k0 + c * 8;
            cp16(cvta_s(sm + s * G1_SLOT + arr * 4096 + swz(row, c)), src);
        }
    };

    const int lr = lane & 15, lc = lane >> 4;

    auto compute = [&](int s) {
        uint32_t base = cvta_s(sm) + (uint32_t)(s * G1_SLOT) * 2;
#pragma unroll
        for (int kk = 0; kk < 2; kk++) {
            int kidx = kk * 2 + lc;
            uint32_t ah[4][4], al[4][4], bh[4][2], bl[4][2];
#pragma unroll
            for (int mi = 0; mi < 4; mi++) {
                int row = wm * 64 + mi * 16 + lr;
                uint32_t off = swz(row, kidx) * 2;
                ldm4(ah[mi][0], ah[mi][1], ah[mi][2], ah[mi][3], base + off);
                ldm4(al[mi][0], al[mi][1], al[mi][2], al[mi][3], base + 4096 * 2 + off);
            }
#pragma unroll
            for (int p = 0; p < 2; p++) {
                int row = wn * 32 + p * 16 + lr;
                uint32_t off = swz(row, kidx) * 2;
                uint32_t r0, r1, r2, r3;
                ldm4(r0, r1, r2, r3, base + 8192 * 2 + off);
                bh[2 * p][0] = r0; bh[2 * p][1] = r2;
                bh[2 * p + 1][0] = r1; bh[2 * p + 1][1] = r3;
                ldm4(r0, r1, r2, r3, base + 12288 * 2 + off);
                bl[2 * p][0] = r0; bl[2 * p][1] = r2;
                bl[2 * p + 1][0] = r1; bl[2 * p + 1][1] = r3;
            }
#pragma unroll
            for (int mi = 0; mi < 4; mi++)
#pragma unroll
                for (int ni = 0; ni < 4; ni++) {
                    mma_bf16(acc[mi][ni], ah[mi], bh[ni]);
                    mma_bf16(acc[mi][ni], al[mi], bh[ni]);
                    mma_bf16(acc[mi][ni], ah[mi], bl[ni]);
                }
        }
    };

    load_stage(0, 0);
    CP_COMMIT();
    load_stage(1, 32);
    CP_COMMIT();
    for (int kc = 0; kc < 32; kc++) {
        CP_WAIT(1);
        __syncthreads();
        // Safe: stage (kc+2)%3 == (kc-1)%3, whose compute finished before the
        // barrier above. Loads issue ahead of this chunk's MMA burst.
        if (kc + 2 < 32) load_stage((kc + 2) % 3, (kc + 2) * 32);
        CP_COMMIT();
        compute(kc % 3);
    }

    // ---- epilogue: stage fp32 tile, then bf16-split into C1[h][b][k2] ----
    CP_WAIT(0);
    __syncthreads();
    float* stg = (float*)dsm;     // [128][132] = 67584 B <= 98304
#pragma unroll
    for (int mi = 0; mi < 4; mi++)
#pragma unroll
        for (int ni = 0; ni < 4; ni++) {
            int r = wm * 64 + mi * 16 + (lane >> 2);
            int c = wn * 32 + ni * 8 + (lane & 3) * 2;
            stg[r * 132 + c]           = acc[mi][ni][0];
            stg[r * 132 + c + 1]       = acc[mi][ni][1];
            stg[(r + 8) * 132 + c]     = acc[mi][ni][2];
            stg[(r + 8) * 132 + c + 1] = acc[mi][ni][3];
        }
    __syncthreads();

    const int kb = bn >> 2;
#pragma unroll
    for (int i = 0; i < 16; i++) {
        int g = i * 256 + t;                   // 4096 groups of 4 k2
        int row = g >> 5, rem = g & 31, h = rem >> 3, kg = rem & 7;
        ushort4 vh, vl;
        bf16 hh, ll;
        split2(stg[row * 132 + (kg * 4 + 0) * 4 + h], hh, ll);
        vh.x = __bfloat16_as_ushort(hh); vl.x = __bfloat16_as_ushort(ll);
        split2(stg[row * 132 + (kg * 4 + 1) * 4 + h], hh, ll);
        vh.y = __bfloat16_as_ushort(hh); vl.y = __bfloat16_as_ushort(ll);
        split2(stg[row * 132 + (kg * 4 + 2) * 4 + h], hh, ll);
        vh.z = __bfloat16_as_ushort(hh); vl.z = __bfloat16_as_ushort(ll);
        split2(stg[row * 132 + (kg * 4 + 3) * 4 + h], hh, ll);
        vh.w = __bfloat16_as_ushort(hh); vl.w = __bfloat16_as_ushort(ll);
        size_t o = ((size_t)h * MTOT + bm + row) * 256 + kb + kg * 4;
        *(ushort4*)(g_c1h + o) = vh;
        *(ushort4*)(g_c1l + o) = vl;
    }
}

// ========================= GEMM2: y = C1_h @ Q2^T + bias ===================
// 256 threads, block 32b x 64n2 x 4h. Warp: h = wid>>1, m-half = wid&1 (16 rows).
// K=256 in 8 chunks of 32. Q2-hi RESIDENT full-K (8 chunked [64][32] tiles);
// A (2pl x 4h x 32 x 32) + Q2-lo ([64][32]) in 3-stage ring, 1 sync/chunk.
// Stage = 8192 + 2048 = 10240 bf16; Bhi resident = 16384 bf16.
#define G2_SLOT  10240
#define G2_BHI   (3 * G2_SLOT)              // 30720 bf16 offset
#define G2_SMEM  ((G2_BHI + 8 * 2048) * 2)  // 94208 B

__global__ __launch_bounds__(256, 2) void gemm2_mma(const float* __restrict__ bias,
                                                    float* __restrict__ Y) {
    extern __shared__ char dsm[];
    bf16* sm = (bf16*)dsm;
    const int t = threadIdx.x, wid = t >> 5, lane = t & 31;
    const int bm = blockIdx.y * 32, bn2 = blockIdx.x * 64;
    const int wh = wid >> 1, mh = wid & 1;     // warp: h = wh, rows mh*16..+15

    float acc[8][4];
#pragma unroll
    for (int b = 0; b < 8; b++)
#pragma unroll
        for (int c = 0; c < 4; c++) acc[b][c] = 0.f;

    auto load_Bhi = [&]() {      // full-K Q2 hi plane, chunked [kc][64][32]
#pragma unroll
        for (int i = 0; i < 8; i++) {
            int gi = i * 256 + t;                    // 2048 x 16B granules
            int kcch = gi >> 8, rem = gi & 255, row = rem >> 2, c = rem & 3;
            const bf16* src = g_q2h + (size_t)(bn2 + row) * 256 + kcch * 32 + c * 8;
            cp16(cvta_s(sm + G2_BHI + kcch * 2048 + swz(row, c)), src);
        }
    };
    auto load_stage = [&](int s, int k0) {
#pragma unroll
        for (int i = 0; i < 5; i++) {
            int gi = i * 256 + t;                    // 1280 x 16B granules
            if (gi < 1024) {       // A: 2pl x 4h x 32 rows x 4 granules
                int pl = gi >> 9, rem = gi & 511;
                int h = rem >> 7, r2 = rem & 127, row = r2 >> 2, c = r2 & 3;
                const bf16* src = (pl ? g_c1l : g_c1h) +
                    ((size_t)h * MTOT + bm + row) * 256 + k0 + c * 8;
                cp16(cvta_s(sm + s * G2_SLOT + pl * 4096 + h * 1024 + swz(row, c)), src);
            } else {               // Blo: 64 rows x 4 granules
                int b = gi - 1024;
                int row = b >> 2, c = b & 3;
                const bf16* src = g_q2l + (size_t)(bn2 + row) * 256 + k0 + c * 8;
                cp16(cvta_s(sm + s * G2_SLOT + 8192 + swz(row, c)), src);
            }
        }
    };

    const int lr = lane & 15, lc = lane >> 4;

    auto compute = [&](int s, int kc) {
        uint32_t abase  = cvta_s(sm) + (uint32_t)(s * G2_SLOT) * 2;
        uint32_t bhbase = cvta_s(sm) + (uint32_t)(G2_BHI + kc * 2048) * 2;
#pragma unroll
        for (int kk = 0; kk < 2; kk++) {
            int kidx = kk * 2 + lc;
            uint32_t ah[4], al[4], bh[8][2], bl[8][2];
            {
                int row = mh * 16 + lr;
                uint32_t off = ((uint32_t)(wh * 1024) + swz(row, kidx)) * 2;
                ldm4(ah[0], ah[1], ah[2], ah[3], abase + off);
                ldm4(al[0], al[1], al[2], al[3], abase + 4096 * 2 + off);
            }
#pragma unroll
            for (int p = 0; p < 4; p++) {
                int row = p * 16 + lr;
                uint32_t off = swz(row, kidx) * 2;
                uint32_t r0, r1, r2, r3;
                ldm4(r0, r1, r2, r3, bhbase + off);
                bh[2 * p][0] = r0; bh[2 * p][1] = r2;
                bh[2 * p + 1][0] = r1; bh[2 * p + 1][1] = r3;
                ldm4(r0, r1, r2, r3, abase + 8192 * 2 + off);
                bl[2 * p][0] = r0; bl[2 * p][1] = r2;
                bl[2 * p + 1][0] = r1; bl[2 * p + 1][1] = r3;
            }
#pragma unroll
            for (int ni = 0; ni < 8; ni++) {
                mma_bf16(acc[ni], ah, bh[ni]);
                mma_bf16(acc[ni], al, bh[ni]);
                mma_bf16(acc[ni], ah, bl[ni]);
            }
        }
    };

    load_Bhi();
    load_stage(0, 0);
    CP_COMMIT();                 // group 0: Bhi + stage0
    load_stage(1, 32);
    CP_COMMIT();                 // group 1: stage1
    for (int kc = 0; kc < 8; kc++) {
        CP_WAIT(1);
        __syncthreads();
        if (kc + 2 < 8) load_stage((kc + 2) % 3, (kc + 2) * 32);
        CP_COMMIT();
        compute(kc % 3, kc);
    }

    // ---- epilogue: reorder (h, n2l) -> col n2l*4+h in smem, coalesced out ----
    CP_WAIT(0);
    __syncthreads();
    float* stg = (float*)dsm;     // [32][260] = 33280 B <= 94208
#pragma unroll
    for (int ni = 0; ni < 8; ni++) {
        int r = mh * 16 + (lane >> 2);
        int n2l = ni * 8 + (lane & 3) * 2;
        stg[r * 260 + n2l * 4 + wh]             = acc[ni][0];
        stg[r * 260 + (n2l + 1) * 4 + wh]       = acc[ni][1];
        stg[(r + 8) * 260 + n2l * 4 + wh]       = acc[ni][2];
        stg[(r + 8) * 260 + (n2l + 1) * 4 + wh] = acc[ni][3];
    }
    __syncthreads();

#pragma unroll
    for (int i = 0; i < 8; i++) {
        int g = i * 256 + t;                    // 2048 float4 groups
        int r = g >> 6, c4 = (g & 63) * 4;
        float4 v = *(const float4*)&stg[r * 260 + c4];
        float4 bz = *(const float4*)(bias + bn2 * 4 + c4);
        v.x += bz.x; v.y += bz.y; v.z += bz.z; v.w += bz.w;
        *(float4*)(Y + (size_t)(bm + r) * 4096 + bn2 * 4 + c4) = v;
    }
}

// ========================= launch ==========================================
extern "C" void kernel_launch(void* const* d_in, const int* in_sizes, int n_in,
                              void* d_out, int out_size) {
    const float* x     = (const float*)d_in[0];
    const float* core0 = (const float*)d_in[1];
    const float* core1 = (const float*)d_in[2];
    const float* core2 = (const float*)d_in[3];
    const float* core3 = (const float*)d_in[4];
    const float* bias  = (const float*)d_in[5];
    float* y = (float*)d_out;

    cudaFuncSetAttribute(gemm1_mma, cudaFuncAttributeMaxDynamicSharedMemorySize, G1_SMEM);
    cudaFuncSetAttribute(gemm2_mma, cudaFuncAttributeMaxDynamicSharedMemorySize, G2_SMEM);

    conv_x_kernel<<<(MTOT * 1024) / (256 * 8), 256>>>(x);
    build_pp_kernel<<<(1024 * 1024) / 256, 256>>>(core2, core3);
    build_q2_kernel<<<(1024 * 256) / 256, 256>>>(core0, core1);

    gemm1_mma<<<dim3(8, 64), 256, G1_SMEM>>>();
    gemm2_mma<<<dim3(16, 256), 256, G2_SMEM>>>(bias, y);
}

// round 8
// speedup vs baseline: 1.2963x; 1.0005x over previous
#include <cuda_runtime.h>
#include <cuda_bf16.h>
#include <cstdint>

// ---------------------------------------------------------------------------
// TR_Linear via two bf16-split GEMMs on the tensor pipe (portable PTX:
// mma.sync.m16n8k16.bf16 / ldmatrix / cp.async).
//   Pp^T[n][i'] (1024x1024), n=(r2*16+r4)*4+h ;  C1 = x @ Pp  (K=1024)
//   Q2^T[n2][k] (1024x256),  k=r2*16+r4, n2=i0*32+i1
//   y[b, n2*4+h] = sum_k C1[b,k*4+h]*Q2[k,n2] + bias
// Precision: v = hi + lo (bf16); D += Ahi*Bhi + Alo*Bhi + Ahi*Blo (fp32 acc)
// R8: TERM-MAJOR MMA ordering -- the three cross-term MMAs for a given
// accumulator are issued 16 (g1) / 8 (g2) MMAs apart instead of back-to-back,
// breaking the accumulator RAW chain that capped tensor pipe at ~50%.
// ---------------------------------------------------------------------------

#define MTOT 8192

typedef __nv_bfloat16 bf16;

__device__ bf16 g_xh[MTOT * 1024];
__device__ bf16 g_xl[MTOT * 1024];
__device__ bf16 g_pph[1024 * 1024];
__device__ bf16 g_ppl[1024 * 1024];
__device__ bf16 g_q2h[1024 * 256];
__device__ bf16 g_q2l[1024 * 256];
__device__ bf16 g_c1h[4 * MTOT * 256];   // [h][b][k2]
__device__ bf16 g_c1l[4 * MTOT * 256];

// ========================= PTX helpers (portable) ==========================
__device__ __forceinline__ void cp16(uint32_t dst, const void* src) {
    asm volatile("cp.async.cg.shared.global [%0], [%1], 16;" :: "r"(dst), "l"(src));
}
#define CP_COMMIT() asm volatile("cp.async.commit_group;" ::: "memory")
#define CP_WAIT(N)  asm volatile("cp.async.wait_group %0;" :: "n"(N) : "memory")

__device__ __forceinline__ void ldm4(uint32_t& r0, uint32_t& r1, uint32_t& r2, uint32_t& r3,
                                     uint32_t addr) {
    asm volatile("ldmatrix.sync.aligned.m8n8.x4.shared.b16 {%0,%1,%2,%3}, [%4];"
                 : "=r"(r0), "=r"(r1), "=r"(r2), "=r"(r3) : "r"(addr));
}
__device__ __forceinline__ void mma_bf16(float* d, const uint32_t* a, const uint32_t* b) {
    asm volatile("mma.sync.aligned.m16n8k16.row.col.f32.bf16.bf16.f32 "
                 "{%0,%1,%2,%3}, {%4,%5,%6,%7}, {%8,%9}, {%0,%1,%2,%3};"
                 : "+f"(d[0]), "+f"(d[1]), "+f"(d[2]), "+f"(d[3])
                 : "r"(a[0]), "r"(a[1]), "r"(a[2]), "r"(a[3]), "r"(b[0]), "r"(b[1]));
}
__device__ __forceinline__ uint32_t cvta_s(const void* p) {
    return (uint32_t)__cvta_generic_to_shared(p);
}
__device__ __forceinline__ void split2(float v, bf16& h, bf16& l) {
    h = __float2bfloat16_rn(v);
    l = __float2bfloat16_rn(v - __bfloat162float(h));
}

// 64B-row swizzle: row stride = 32 bf16 (64B); 16B granule c (0..3) stored at
// physical granule c ^ ((row>>1)&3). Conflict-free for ldmatrix + cp.async.
__device__ __forceinline__ uint32_t swz(int row, int c) {
    return (uint32_t)(row * 32 + ((c ^ ((row >> 1) & 3)) * 8));
}

// ========================= prepass kernels =================================
__global__ void conv_x_kernel(const float* __restrict__ x) {
    int i = (blockIdx.x * blockDim.x + threadIdx.x) * 8;
    float4 v0 = *(const float4*)(x + i);
    float4 v1 = *(const float4*)(x + i + 4);
    ushort4 h0, h1, l0, l1;
    bf16 hh, ll;
    split2(v0.x, hh, ll); h0.x = __bfloat16_as_ushort(hh); l0.x = __bfloat16_as_ushort(ll);
    split2(v0.y, hh, ll); h0.y = __bfloat16_as_ushort(hh); l0.y = __bfloat16_as_ushort(ll);
    split2(v0.z, hh, ll); h0.z = __bfloat16_as_ushort(hh); l0.z = __bfloat16_as_ushort(ll);
    split2(v0.w, hh, ll); h0.w = __bfloat16_as_ushort(hh); l0.w = __bfloat16_as_ushort(ll);
    split2(v1.x, hh, ll); h1.x = __bfloat16_as_ushort(hh); l1.x = __bfloat16_as_ushort(ll);
    split2(v1.y, hh, ll); h1.y = __bfloat16_as_ushort(hh); l1.y = __bfloat16_as_ushort(ll);
    split2(v1.z, hh, ll); h1.z = __bfloat16_as_ushort(hh); l1.z = __bfloat16_as_ushort(ll);
    split2(v1.w, hh, ll); h1.w = __bfloat16_as_ushort(hh); l1.w = __bfloat16_as_ushort(ll);
    *(ushort4*)(g_xh + i)     = h0;
    *(ushort4*)(g_xh + i + 4) = h1;
    *(ushort4*)(g_xl + i)     = l0;
    *(ushort4*)(g_xl + i + 4) = l1;
}

__global__ void build_pp_kernel(const float* __restrict__ c2, const float* __restrict__ c3) {
    int idx = blockIdx.x * blockDim.x + threadIdx.x;   // n*1024 + i'
    int n = idx >> 10, ip = idx & 1023;
    int r2 = n >> 6, r4 = (n >> 2) & 15, h = n & 3;
    int o0 = h * 16 + (ip >> 6), o1 = ip & 63;
    const float* a = c2 + (r2 * 64 + o0) * 16;
    float s = 0.f;
#pragma unroll
    for (int r3 = 0; r3 < 16; r3++) s += a[r3] * c3[(r3 * 64 + o1) * 16 + r4];
    bf16 hh, ll;
    split2(s, hh, ll);
    g_pph[idx] = hh;
    g_ppl[idx] = ll;
}

__global__ void build_q2_kernel(const float* __restrict__ c0, const float* __restrict__ c1) {
    int idx = blockIdx.x * blockDim.x + threadIdx.x;   // n2*256 + k
    int n2 = idx >> 8, k = idx & 255;
    int r2 = k >> 4, r4 = k & 15;
    int i0 = n2 >> 5, i1 = n2 & 31;
    const float* a = c0 + (r4 * 32 + i0) * 16;
    float s = 0.f;
#pragma unroll
    for (int r1 = 0; r1 < 16; r1++) s += a[r1] * c1[(r1 * 32 + i1) * 16 + r2];
    bf16 hh, ll;
    split2(s, hh, ll);
    g_q2h[idx] = hh;
    g_q2l[idx] = ll;
}

// ========================= GEMM1: C1 = x @ Pp ==============================
// 128x128 block tile, 256 threads (8 warps, warp tile 64x32).
// K=1024 in 32 chunks of 32. 3-stage ring, swizzled 64B rows.
// Stage layout (bf16 elems): Ah[128][32] @0, Al @4096, Bh @8192, Bl @12288.
#define G1_SLOT  16384                       // bf16 per stage (32768 B)
#define G1_SMEM  (3 * G1_SLOT * 2)           // 98304 B

__global__ __launch_bounds__(256, 2) void gemm1_mma() {
    extern __shared__ char dsm[];
    bf16* sm = (bf16*)dsm;
    const int t = threadIdx.x, wid = t >> 5, lane = t & 31;
    const int bm = blockIdx.y * 128, bn = blockIdx.x * 128;
    const int wm = wid & 1, wn = wid >> 1;     // warp tile 64m x 32n

    float acc[4][4][4];
#pragma unroll
    for (int a = 0; a < 4; a++)
#pragma unroll
        for (int b = 0; b < 4; b++)
#pragma unroll
            for (int c = 0; c < 4; c++) acc[a][b][c] = 0.f;

    auto load_stage = [&](int s, int k0) {
#pragma unroll
        for (int i = 0; i < 8; i++) {
            int gi = i * 256 + t;                      // 2048 x 16B granules
            int arr = gi >> 9, rem = gi & 511, row = rem >> 2, c = rem & 3;
            const bf16* src;
            if (arr == 0)      src = g_xh  + (size_t)(bm + row) * 1024 + k0 + c * 8;
            else if (arr == 1) src = g_xl  + (size_t)(bm + row) * 1024 + k0 + c * 8;
            else if (arr == 2) src = g_pph + (size_t)(bn + row) * 1024 + k0 + c * 8;
            else               src = g_ppl + (size_t)(bn + row) * 1024 + k0 + c * 8;
            cp16(cvta_s(sm + s * G1_SLOT + arr * 4096 + swz(row, c)), src);
        }
    };

    const int lr = lane & 15, lc = lane >> 4;

    auto compute = [&](int s) {
        uint32_t base = cvta_s(sm) + (uint32_t)(s * G1_SLOT) * 2;
#pragma unroll
        for (int kk = 0; kk < 2; kk++) {
            int kidx = kk * 2 + lc;
            uint32_t ah[4][4], al[4][4], bh[4][2], bl[4][2];
#pragma unroll
            for (int mi = 0; mi < 4; mi++) {
                int row = wm * 64 + mi * 16 + lr;
                uint32_t off = swz(row, kidx) * 2;
                ldm4(ah[mi][0], ah[mi][1], ah[mi][2], ah[mi][3], base + off);
                ldm4(al[mi][0], al[mi][1], al[mi][2], al[mi][3], base + 4096 * 2 + off);
            }
#pragma unroll
            for (int p = 0; p < 2; p++) {
                int row = wn * 32 + p * 16 + lr;
                uint32_t off = swz(row, kidx) * 2;
                uint32_t r0, r1, r2, r3;
                ldm4(r0, r1, r2, r3, base + 8192 * 2 + off);
                bh[2 * p][0] = r0; bh[2 * p][1] = r2;
                bh[2 * p + 1][0] = r1; bh[2 * p + 1][1] = r3;
                ldm4(r0, r1, r2, r3, base + 12288 * 2 + off);
                bl[2 * p][0] = r0; bl[2 * p][1] = r2;
                bl[2 * p + 1][0] = r1; bl[2 * p + 1][1] = r3;
            }
            // TERM-MAJOR: same accumulator reused at distance 16 MMAs.
#pragma unroll
            for (int mi = 0; mi < 4; mi++)
#pragma unroll
                for (int ni = 0; ni < 4; ni++)
                    mma_bf16(acc[mi][ni], ah[mi], bh[ni]);
#pragma unroll
            for (int mi = 0; mi < 4; mi++)
#pragma unroll
                for (int ni = 0; ni < 4; ni++)
                    mma_bf16(acc[mi][ni], al[mi], bh[ni]);
#pragma unroll
            for (int mi = 0; mi < 4; mi++)
#pragma unroll
                for (int ni = 0; ni < 4; ni++)
                    mma_bf16(acc[mi][ni], ah[mi], bl[ni]);
        }
    };

    load_stage(0, 0);
    CP_COMMIT();
    load_stage(1, 32);
    CP_COMMIT();
    for (int kc = 0; kc < 32; kc++) {
        CP_WAIT(1);
        __syncthreads();
        if (kc + 2 < 32) load_stage((kc + 2) % 3, (kc + 2) * 32);
        CP_COMMIT();
        compute(kc % 3);
    }

    // ---- epilogue: stage fp32 tile, then bf16-split into C1[h][b][k2] ----
    CP_WAIT(0);
    __syncthreads();
    float* stg = (float*)dsm;     // [128][132] = 67584 B <= 98304
#pragma unroll
    for (int mi = 0; mi < 4; mi++)
#pragma unroll
        for (int ni = 0; ni < 4; ni++) {
            int r = wm * 64 + mi * 16 + (lane >> 2);
            int c = wn * 32 + ni * 8 + (lane & 3) * 2;
            stg[r * 132 + c]           = acc[mi][ni][0];
            stg[r * 132 + c + 1]       = acc[mi][ni][1];
            stg[(r + 8) * 132 + c]     = acc[mi][ni][2];
            stg[(r + 8) * 132 + c + 1] = acc[mi][ni][3];
        }
    __syncthreads();

    const int kb = bn >> 2;
#pragma unroll
    for (int i = 0; i < 16; i++) {
        int g = i * 256 + t;                   // 4096 groups of 4 k2
        int row = g >> 5, rem = g & 31, h = rem >> 3, kg = rem & 7;
        ushort4 vh, vl;
        bf16 hh, ll;
        split2(stg[row * 132 + (kg * 4 + 0) * 4 + h], hh, ll);
        vh.x = __bfloat16_as_ushort(hh); vl.x = __bfloat16_as_ushort(ll);
        split2(stg[row * 132 + (kg * 4 + 1) * 4 + h], hh, ll);
        vh.y = __bfloat16_as_ushort(hh); vl.y = __bfloat16_as_ushort(ll);
        split2(stg[row * 132 + (kg * 4 + 2) * 4 + h], hh, ll);
        vh.z = __bfloat16_as_ushort(hh); vl.z = __bfloat16_as_ushort(ll);
        split2(stg[row * 132 + (kg * 4 + 3) * 4 + h], hh, ll);
        vh.w = __bfloat16_as_ushort(hh); vl.w = __bfloat16_as_ushort(ll);
        size_t o = ((size_t)h * MTOT + bm + row) * 256 + kb + kg * 4;
        *(ushort4*)(g_c1h + o) = vh;
        *(ushort4*)(g_c1l + o) = vl;
    }
}

// ========================= GEMM2: y = C1_h @ Q2^T + bias ===================
// 256 threads, block 32b x 64n2 x 4h. Warp: h = wid>>1, m-half = wid&1 (16 rows).
// K=256 in 8 chunks of 32. Q2-hi RESIDENT full-K (8 chunked [64][32] tiles);
// A (2pl x 4h x 32 x 32) + Q2-lo ([64][32]) in 3-stage ring, 1 sync/chunk.
#define G2_SLOT  10240
#define G2_BHI   (3 * G2_SLOT)              // 30720 bf16 offset
#define G2_SMEM  ((G2_BHI + 8 * 2048) * 2)  // 94208 B

__global__ __launch_bounds__(256, 2) void gemm2_mma(const float* __restrict__ bias,
                                                    float* __restrict__ Y) {
    extern __shared__ char dsm[];
    bf16* sm = (bf16*)dsm;
    const int t = threadIdx.x, wid = t >> 5, lane = t & 31;
    const int bm = blockIdx.y * 32, bn2 = blockIdx.x * 64;
    const int wh = wid >> 1, mh = wid & 1;     // warp: h = wh, rows mh*16..+15

    float acc[8][4];
#pragma unroll
    for (int b = 0; b < 8; b++)
#pragma unroll
        for (int c = 0; c < 4; c++) acc[b][c] = 0.f;

    auto load_Bhi = [&]() {      // full-K Q2 hi plane, chunked [kc][64][32]
#pragma unroll
        for (int i = 0; i < 8; i++) {
            int gi = i * 256 + t;                    // 2048 x 16B granules
            int kcch = gi >> 8, rem = gi & 255, row = rem >> 2, c = rem & 3;
            const bf16* src = g_q2h + (size_t)(bn2 + row) * 256 + kcch * 32 + c * 8;
            cp16(cvta_s(sm + G2_BHI + kcch * 2048 + swz(row, c)), src);
        }
    };
    auto load_stage = [&](int s, int k0) {
#pragma unroll
        for (int i = 0; i < 5; i++) {
            int gi = i * 256 + t;                    // 1280 x 16B granules
            if (gi < 1024) {       // A: 2pl x 4h x 32 rows x 4 granules
                int pl = gi >> 9, rem = gi & 511;
                int h = rem >> 7, r2 = rem & 127, row = r2 >> 2, c = r2 & 3;
                const bf16* src = (pl ? g_c1l : g_c1h) +
                    ((size_t)h * MTOT + bm + row) * 256 + k0 + c * 8;
                cp16(cvta_s(sm + s * G2_SLOT + pl * 4096 + h * 1024 + swz(row, c)), src);
            } else {               // Blo: 64 rows x 4 granules
                int b = gi - 1024;
                int row = b >> 2, c = b & 3;
                const bf16* src = g_q2l + (size_t)(bn2 + row) * 256 + k0 + c * 8;
                cp16(cvta_s(sm + s * G2_SLOT + 8192 + swz(row, c)), src);
            }
        }
    };

    const int lr = lane & 15, lc = lane >> 4;

    auto compute = [&](int s, int kc) {
        uint32_t abase  = cvta_s(sm) + (uint32_t)(s * G2_SLOT) * 2;
        uint32_t bhbase = cvta_s(sm) + (uint32_t)(G2_BHI + kc * 2048) * 2;
#pragma unroll
        for (int kk = 0; kk < 2; kk++) {
            int kidx = kk * 2 + lc;
            uint32_t ah[4], al[4], bh[8][2], bl[8][2];
            {
                int row = mh * 16 + lr;
                uint32_t off = ((uint32_t)(wh * 1024) + swz(row, kidx)) * 2;
                ldm4(ah[0], ah[1], ah[2], ah[3], abase + off);
                ldm4(al[0], al[1], al[2], al[3], abase + 4096 * 2 + off);
            }
#pragma unroll
            for (int p = 0; p < 4; p++) {
                int row = p * 16 + lr;
                uint32_t off = swz(row, kidx) * 2;
                uint32_t r0, r1, r2, r3;
                ldm4(r0, r1, r2, r3, bhbase + off);
                bh[2 * p][0] = r0; bh[2 * p][1] = r2;
                bh[2 * p + 1][0] = r1; bh[2 * p + 1][1] = r3;
                ldm4(r0, r1, r2, r3, abase + 8192 * 2 + off);
                bl[2 * p][0] = r0; bl[2 * p][1] = r2;
                bl[2 * p + 1][0] = r1; bl[2 * p + 1][1] = r3;
            }
            // TERM-MAJOR: same accumulator reused at distance 8 MMAs.
#pragma unroll
            for (int ni = 0; ni < 8; ni++)
                mma_bf16(acc[ni], ah, bh[ni]);
#pragma unroll
            for (int ni = 0; ni < 8; ni++)
                mma_bf16(acc[ni], al, bh[ni]);
#pragma unroll
            for (int ni = 0; ni < 8; ni++)
                mma_bf16(acc[ni], ah, bl[ni]);
        }
    };

    load_Bhi();
    load_stage(0, 0);
    CP_COMMIT();                 // group 0: Bhi + stage0
    load_stage(1, 32);
    CP_COMMIT();                 // group 1: stage1
    for (int kc = 0; kc < 8; kc++) {
        CP_WAIT(1);
        __syncthreads();
        if (kc + 2 < 8) load_stage((kc + 2) % 3, (kc + 2) * 32);
        CP_COMMIT();
        compute(kc % 3, kc);
    }

    // ---- epilogue: reorder (h, n2l) -> col n2l*4+h in smem, coalesced out ----
    CP_WAIT(0);
    __syncthreads();
    float* stg = (float*)dsm;     // [32][260] = 33280 B <= 94208
#pragma unroll
    for (int ni = 0; ni < 8; ni++) {
        int r = mh * 16 + (lane >> 2);
        int n2l = ni * 8 + (lane & 3) * 2;
        stg[r * 260 + n2l * 4 + wh]             = acc[ni][0];
        stg[r * 260 + (n2l + 1) * 4 + wh]       = acc[ni][1];
        stg[(r + 8) * 260 + n2l * 4 + wh]       = acc[ni][2];
        stg[(r + 8) * 260 + (n2l + 1) * 4 + wh] = acc[ni][3];
    }
    __syncthreads();

#pragma unroll
    for (int i = 0; i < 8; i++) {
        int g = i * 256 + t;                    // 2048 float4 groups
        int r = g >> 6, c4 = (g & 63) * 4;
        float4 v = *(const float4*)&stg[r * 260 + c4];
        float4 bz = *(const float4*)(bias + bn2 * 4 + c4);
        v.x += bz.x; v.y += bz.y; v.z += bz.z; v.w += bz.w;
        *(float4*)(Y + (size_t)(bm + r) * 4096 + bn2 * 4 + c4) = v;
    }
}

// ========================= launch ==========================================
extern "C" void kernel_launch(void* const* d_in, const int* in_sizes, int n_in,
                              void* d_out, int out_size) {
    const float* x     = (const float*)d_in[0];
    const float* core0 = (const float*)d_in[1];
    const float* core1 = (const float*)d_in[2];
    const float* core2 = (const float*)d_in[3];
    const float* core3 = (const float*)d_in[4];
    const float* bias  = (const float*)d_in[5];
    float* y = (float*)d_out;

    cudaFuncSetAttribute(gemm1_mma, cudaFuncAttributeMaxDynamicSharedMemorySize, G1_SMEM);
    cudaFuncSetAttribute(gemm2_mma, cudaFuncAttributeMaxDynamicSharedMemorySize, G2_SMEM);

    conv_x_kernel<<<(MTOT * 1024) / (256 * 8), 256>>>(x);
    build_pp_kernel<<<(1024 * 1024) / 256, 256>>>(core2, core3);
    build_q2_kernel<<<(1024 * 256) / 256, 256>>>(core0, core1);

    gemm1_mma<<<dim3(8, 64), 256, G1_SMEM>>>();
    gemm2_mma<<<dim3(16, 256), 256, G2_SMEM>>>(bias, y);
}

// round 9
// speedup vs baseline: 1.7336x; 1.3373x over previous
#include <cuda_runtime.h>
#include <cuda_fp16.h>
#include <cstdint>

// ---------------------------------------------------------------------------
// TR_Linear via two fp16 GEMMs on the tensor pipe (portable PTX:
// mma.sync.m16n8k16.f16 / ldmatrix / cp.async).
//   Pp^T[n][i'] (1024x1024), n=(r2*16+r4)*4+h ;  C1 = x @ Pp  (K=1024)
//   Q2^T[n2][k] (1024x256),  k=r2*16+r4, n2=i0*32+i1
//   y[b, n2*4+h] = sum_k C1[b,k*4+h]*Q2[k,n2] + bias
// Precision (R9): A = fp16 hi + fp16 lo (A exact to ~2^-22); B = single fp16.
// D = Ahi*B + Alo*B (fp32 acc). Error ~ B's fp16 quantization ~ 3-5e-4 norm.
// 2 MMA products instead of 3 -> 1.5x fewer HMMAs (the measured wall).
// ---------------------------------------------------------------------------

#define MTOT 8192

typedef __half fp16;

__device__ fp16 g_xh[MTOT * 1024];
__device__ fp16 g_xl[MTOT * 1024];
__device__ fp16 g_pp[1024 * 1024];
__device__ fp16 g_q2[1024 * 256];
__device__ fp16 g_c1h[4 * MTOT * 256];   // [h][b][k2]
__device__ fp16 g_c1l[4 * MTOT * 256];

// ========================= PTX helpers (portable) ==========================
__device__ __forceinline__ void cp16(uint32_t dst, const void* src) {
    asm volatile("cp.async.cg.shared.global [%0], [%1], 16;" :: "r"(dst), "l"(src));
}
#define CP_COMMIT() asm volatile("cp.async.commit_group;" ::: "memory")
#define CP_WAIT(N)  asm volatile("cp.async.wait_group %0;" :: "n"(N) : "memory")

__device__ __forceinline__ void ldm4(uint32_t& r0, uint32_t& r1, uint32_t& r2, uint32_t& r3,
                                     uint32_t addr) {
    asm volatile("ldmatrix.sync.aligned.m8n8.x4.shared.b16 {%0,%1,%2,%3}, [%4];"
                 : "=r"(r0), "=r"(r1), "=r"(r2), "=r"(r3) : "r"(addr));
}
__device__ __forceinline__ void mma_fp16(float* d, const uint32_t* a, const uint32_t* b) {
    asm volatile("mma.sync.aligned.m16n8k16.row.col.f32.f16.f16.f32 "
                 "{%0,%1,%2,%3}, {%4,%5,%6,%7}, {%8,%9}, {%0,%1,%2,%3};"
                 : "+f"(d[0]), "+f"(d[1]), "+f"(d[2]), "+f"(d[3])
                 : "r"(a[0]), "r"(a[1]), "r"(a[2]), "r"(a[3]), "r"(b[0]), "r"(b[1]));
}
__device__ __forceinline__ uint32_t cvta_s(const void* p) {
    return (uint32_t)__cvta_generic_to_shared(p);
}
__device__ __forceinline__ void split2h(float v, fp16& h, fp16& l) {
    h = __float2half_rn(v);
    l = __float2half_rn(v - __half2float(h));
}

// 64B-row swizzle: row stride = 32 fp16 (64B); 16B granule c (0..3) stored at
// physical granule c ^ ((row>>1)&3). Conflict-free for ldmatrix + cp.async.
__device__ __forceinline__ uint32_t swz(int row, int c) {
    return (uint32_t)(row * 32 + ((c ^ ((row >> 1) & 3)) * 8));
}

// ========================= prepass kernels =================================
__global__ void conv_x_kernel(const float* __restrict__ x) {
    int i = (blockIdx.x * blockDim.x + threadIdx.x) * 8;
    float4 v0 = *(const float4*)(x + i);
    float4 v1 = *(const float4*)(x + i + 4);
    ushort4 h0, h1, l0, l1;
    fp16 hh, ll;
    split2h(v0.x, hh, ll); h0.x = __half_as_ushort(hh); l0.x = __half_as_ushort(ll);
    split2h(v0.y, hh, ll); h0.y = __half_as_ushort(hh); l0.y = __half_as_ushort(ll);
    split2h(v0.z, hh, ll); h0.z = __half_as_ushort(hh); l0.z = __half_as_ushort(ll);
    split2h(v0.w, hh, ll); h0.w = __half_as_ushort(hh); l0.w = __half_as_ushort(ll);
    split2h(v1.x, hh, ll); h1.x = __half_as_ushort(hh); l1.x = __half_as_ushort(ll);
    split2h(v1.y, hh, ll); h1.y = __half_as_ushort(hh); l1.y = __half_as_ushort(ll);
    split2h(v1.z, hh, ll); h1.z = __half_as_ushort(hh); l1.z = __half_as_ushort(ll);
    split2h(v1.w, hh, ll); h1.w = __half_as_ushort(hh); l1.w = __half_as_ushort(ll);
    *(ushort4*)(g_xh + i)     = h0;
    *(ushort4*)(g_xh + i + 4) = h1;
    *(ushort4*)(g_xl + i)     = l0;
    *(ushort4*)(g_xl + i + 4) = l1;
}

__global__ void build_pp_kernel(const float* __restrict__ c2, const float* __restrict__ c3) {
    int idx = blockIdx.x * blockDim.x + threadIdx.x;   // n*1024 + i'
    int n = idx >> 10, ip = idx & 1023;
    int r2 = n >> 6, r4 = (n >> 2) & 15, h = n & 3;
    int o0 = h * 16 + (ip >> 6), o1 = ip & 63;
    const float* a = c2 + (r2 * 64 + o0) * 16;
    float s = 0.f;
#pragma unroll
    for (int r3 = 0; r3 < 16; r3++) s += a[r3] * c3[(r3 * 64 + o1) * 16 + r4];
    g_pp[idx] = __float2half_rn(s);
}

__global__ void build_q2_kernel(const float* __restrict__ c0, const float* __restrict__ c1) {
    int idx = blockIdx.x * blockDim.x + threadIdx.x;   // n2*256 + k
    int n2 = idx >> 8, k = idx & 255;
    int r2 = k >> 4, r4 = k & 15;
    int i0 = n2 >> 5, i1 = n2 & 31;
    const float* a = c0 + (r4 * 32 + i0) * 16;
    float s = 0.f;
#pragma unroll
    for (int r1 = 0; r1 < 16; r1++) s += a[r1] * c1[(r1 * 32 + i1) * 16 + r2];
    g_q2[idx] = __float2half_rn(s);
}

// ========================= GEMM1: C1 = x @ Pp ==============================
// 128x128 block tile, 256 threads (8 warps, warp tile 64x32).
// K=1024 in 32 chunks of 32. 3-stage ring, swizzled 64B rows.
// Stage layout (fp16 elems): Ah[128][32] @0, Al @4096, B @8192.
#define G1_SLOT  12288                       // fp16 per stage (24576 B)
#define G1_SMEM  (3 * G1_SLOT * 2)           // 73728 B

__global__ __launch_bounds__(256, 2) void gemm1_mma() {
    extern __shared__ char dsm[];
    fp16* sm = (fp16*)dsm;
    const int t = threadIdx.x, wid = t >> 5, lane = t & 31;
    const int bm = blockIdx.y * 128, bn = blockIdx.x * 128;
    const int wm = wid & 1, wn = wid >> 1;     // warp tile 64m x 32n

    float acc[4][4][4];
#pragma unroll
    for (int a = 0; a < 4; a++)
#pragma unroll
        for (int b = 0; b < 4; b++)
#pragma unroll
            for (int c = 0; c < 4; c++) acc[a][b][c] = 0.f;

    auto load_stage = [&](int s, int k0) {
#pragma unroll
        for (int i = 0; i < 6; i++) {
            int gi = i * 256 + t;                      // 1536 x 16B granules
            int arr = gi >> 9, rem = gi & 511, row = rem >> 2, c = rem & 3;
            const fp16* src;
            if (arr == 0)      src = g_xh + (size_t)(bm + row) * 1024 + k0 + c * 8;
            else if (arr == 1) src = g_xl + (size_t)(bm + row) * 1024 + k0 + c * 8;
            else               src = g_pp + (size_t)(bn + row) * 1024 + k0 + c * 8;
            cp16(cvta_s(sm + s * G1_SLOT + arr * 4096 + swz(row, c)), src);
        }
    };

    const int lr = lane & 15, lc = lane >> 4;

    auto compute = [&](int s) {
        uint32_t base = cvta_s(sm) + (uint32_t)(s * G1_SLOT) * 2;
#pragma unroll
        for (int kk = 0; kk < 2; kk++) {
            int kidx = kk * 2 + lc;
            uint32_t ah[4][4], al[4][4], bh[4][2];
#pragma unroll
            for (int mi = 0; mi < 4; mi++) {
                int row = wm * 64 + mi * 16 + lr;
                uint32_t off = swz(row, kidx) * 2;
                ldm4(ah[mi][0], ah[mi][1], ah[mi][2], ah[mi][3], base + off);
                ldm4(al[mi][0], al[mi][1], al[mi][2], al[mi][3], base + 4096 * 2 + off);
            }
#pragma unroll
            for (int p = 0; p < 2; p++) {
                int row = wn * 32 + p * 16 + lr;
                uint32_t off = swz(row, kidx) * 2;
                uint32_t r0, r1, r2, r3;
                ldm4(r0, r1, r2, r3, base + 8192 * 2 + off);
                bh[2 * p][0] = r0; bh[2 * p][1] = r2;
                bh[2 * p + 1][0] = r1; bh[2 * p + 1][1] = r3;
            }
#pragma unroll
            for (int mi = 0; mi < 4; mi++)
#pragma unroll
                for (int ni = 0; ni < 4; ni++)
                    mma_fp16(acc[mi][ni], ah[mi], bh[ni]);
#pragma unroll
            for (int mi = 0; mi < 4; mi++)
#pragma unroll
                for (int ni = 0; ni < 4; ni++)
                    mma_fp16(acc[mi][ni], al[mi], bh[ni]);
        }
    };

    load_stage(0, 0);
    CP_COMMIT();
    load_stage(1, 32);
    CP_COMMIT();
    for (int kc = 0; kc < 32; kc++) {
        CP_WAIT(1);
        __syncthreads();
        if (kc + 2 < 32) load_stage((kc + 2) % 3, (kc + 2) * 32);
        CP_COMMIT();
        compute(kc % 3);
    }

    // ---- epilogue: stage fp32 tile, then fp16-split into C1[h][b][k2] ----
    CP_WAIT(0);
    __syncthreads();
    float* stg = (float*)dsm;     // [128][132] = 67584 B <= 73728
#pragma unroll
    for (int mi = 0; mi < 4; mi++)
#pragma unroll
        for (int ni = 0; ni < 4; ni++) {
            int r = wm * 64 + mi * 16 + (lane >> 2);
            int c = wn * 32 + ni * 8 + (lane & 3) * 2;
            stg[r * 132 + c]           = acc[mi][ni][0];
            stg[r * 132 + c + 1]       = acc[mi][ni][1];
            stg[(r + 8) * 132 + c]     = acc[mi][ni][2];
            stg[(r + 8) * 132 + c + 1] = acc[mi][ni][3];
        }
    __syncthreads();

    const int kb = bn >> 2;
#pragma unroll
    for (int i = 0; i < 16; i++) {
        int g = i * 256 + t;                   // 4096 groups of 4 k2
        int row = g >> 5, rem = g & 31, h = rem >> 3, kg = rem & 7;
        ushort4 vh, vl;
        fp16 hh, ll;
        split2h(stg[row * 132 + (kg * 4 + 0) * 4 + h], hh, ll);
        vh.x = __half_as_ushort(hh); vl.x = __half_as_ushort(ll);
        split2h(stg[row * 132 + (kg * 4 + 1) * 4 + h], hh, ll);
        vh.y = __half_as_ushort(hh); vl.y = __half_as_ushort(ll);
        split2h(stg[row * 132 + (kg * 4 + 2) * 4 + h], hh, ll);
        vh.z = __half_as_ushort(hh); vl.z = __half_as_ushort(ll);
        split2h(stg[row * 132 + (kg * 4 + 3) * 4 + h], hh, ll);
        vh.w = __half_as_ushort(hh); vl.w = __half_as_ushort(ll);
        size_t o = ((size_t)h * MTOT + bm + row) * 256 + kb + kg * 4;
        *(ushort4*)(g_c1h + o) = vh;
        *(ushort4*)(g_c1l + o) = vl;
    }
}

// ========================= GEMM2: y = C1_h @ Q2^T + bias ===================
// 256 threads, block 32b x 64n2 x 4h. Warp: h = wid>>1, m-half = wid&1 (16 rows).
// K=256 in 8 chunks of 32. Q2 RESIDENT full-K (8 chunked [64][32] tiles);
// A (2pl x 4h x 32 x 32) in 3-stage ring, 1 sync/chunk.
#define G2_SLOT  8192
#define G2_BHI   (3 * G2_SLOT)              // 24576 fp16 offset
#define G2_SMEM  ((G2_BHI + 8 * 2048) * 2)  // 81920 B

__global__ __launch_bounds__(256, 2) void gemm2_mma(const float* __restrict__ bias,
                                                    float* __restrict__ Y) {
    extern __shared__ char dsm[];
    fp16* sm = (fp16*)dsm;
    const int t = threadIdx.x, wid = t >> 5, lane = t & 31;
    const int bm = blockIdx.y * 32, bn2 = blockIdx.x * 64;
    const int wh = wid >> 1, mh = wid & 1;     // warp: h = wh, rows mh*16..+15

    float acc[8][4];
#pragma unroll
    for (int b = 0; b < 8; b++)
#pragma unroll
        for (int c = 0; c < 4; c++) acc[b][c] = 0.f;

    auto load_B = [&]() {        // full-K Q2, chunked [kc][64][32]
#pragma unroll
        for (int i = 0; i < 8; i++) {
            int gi = i * 256 + t;                    // 2048 x 16B granules
            int kcch = gi >> 8, rem = gi & 255, row = rem >> 2, c = rem & 3;
            const fp16* src = g_q2 + (size_t)(bn2 + row) * 256 + kcch * 32 + c * 8;
            cp16(cvta_s(sm + G2_BHI + kcch * 2048 + swz(row, c)), src);
        }
    };
    auto load_stage = [&](int s, int k0) {
#pragma unroll
        for (int i = 0; i < 4; i++) {
            int gi = i * 256 + t;                    // 1024 x 16B granules
            int pl = gi >> 9, rem = gi & 511;
            int h = rem >> 7, r2 = rem & 127, row = r2 >> 2, c = r2 & 3;
            const fp16* src = (pl ? g_c1l : g_c1h) +
                ((size_t)h * MTOT + bm + row) * 256 + k0 + c * 8;
            cp16(cvta_s(sm + s * G2_SLOT + pl * 4096 + h * 1024 + swz(row, c)), src);
        }
    };

    const int lr = lane & 15, lc = lane >> 4;

    auto compute = [&](int s, int kc) {
        uint32_t abase  = cvta_s(sm) + (uint32_t)(s * G2_SLOT) * 2;
        uint32_t bhbase = cvta_s(sm) + (uint32_t)(G2_BHI + kc * 2048) * 2;
#pragma unroll
        for (int kk = 0; kk < 2; kk++) {
            int kidx = kk * 2 + lc;
            uint32_t ah[4], al[4], bh[8][2];
            {
                int row = mh * 16 + lr;
                uint32_t off = ((uint32_t)(wh * 1024) + swz(row, kidx)) * 2;
                ldm4(ah[0], ah[1], ah[2], ah[3], abase + off);
                ldm4(al[0], al[1], al[2], al[3], abase + 4096 * 2 + off);
            }
#pragma unroll
            for (int p = 0; p < 4; p++) {
                int row = p * 16 + lr;
                uint32_t off = swz(row, kidx) * 2;
                uint32_t r0, r1, r2, r3;
                ldm4(r0, r1, r2, r3, bhbase + off);
                bh[2 * p][0] = r0; bh[2 * p][1] = r2;
                bh[2 * p + 1][0] = r1; bh[2 * p + 1][1] = r3;
            }
#pragma unroll
            for (int ni = 0; ni < 8; ni++)
                mma_fp16(acc[ni], ah, bh[ni]);
#pragma unroll
            for (int ni = 0; ni < 8; ni++)
                mma_fp16(acc[ni], al, bh[ni]);
        }
    };

    load_B();
    load_stage(0, 0);
    CP_COMMIT();                 // group 0: B + stage0
    load_stage(1, 32);
    CP_COMMIT();                 // group 1: stage1
    for (int kc = 0; kc < 8; kc++) {
        CP_WAIT(1);
        __syncthreads();
        if (kc + 2 < 8) load_stage((kc + 2) % 3, (kc + 2) * 32);
        CP_COMMIT();
        compute(kc % 3, kc);
    }

    // ---- epilogue: reorder (h, n2l) -> col n2l*4+h in smem, coalesced out ----
    CP_WAIT(0);
    __syncthreads();
    float* stg = (float*)dsm;     // [32][260] = 33280 B <= 81920
#pragma unroll
    for (int ni = 0; ni < 8; ni++) {
        int r = mh * 16 + (lane >> 2);
        int n2l = ni * 8 + (lane & 3) * 2;
        stg[r * 260 + n2l * 4 + wh]             = acc[ni][0];
        stg[r * 260 + (n2l + 1) * 4 + wh]       = acc[ni][1];
        stg[(r + 8) * 260 + n2l * 4 + wh]       = acc[ni][2];
        stg[(r + 8) * 260 + (n2l + 1) * 4 + wh] = acc[ni][3];
    }
    __syncthreads();

#pragma unroll
    for (int i = 0; i < 8; i++) {
        int g = i * 256 + t;                    // 2048 float4 groups
        int r = g >> 6, c4 = (g & 63) * 4;
        float4 v = *(const float4*)&stg[r * 260 + c4];
        float4 bz = *(const float4*)(bias + bn2 * 4 + c4);
        v.x += bz.x; v.y += bz.y; v.z += bz.z; v.w += bz.w;
        *(float4*)(Y + (size_t)(bm + r) * 4096 + bn2 * 4 + c4) = v;
    }
}

// ========================= launch ==========================================
extern "C" void kernel_launch(void* const* d_in, const int* in_sizes, int n_in,
                              void* d_out, int out_size) {
    const float* x     = (const float*)d_in[0];
    const float* core0 = (const float*)d_in[1];
    const float* core1 = (const float*)d_in[2];
    const float* core2 = (const float*)d_in[3];
    const float* core3 = (const float*)d_in[4];
    const float* bias  = (const float*)d_in[5];
    float* y = (float*)d_out;

    cudaFuncSetAttribute(gemm1_mma, cudaFuncAttributeMaxDynamicSharedMemorySize, G1_SMEM);
    cudaFuncSetAttribute(gemm2_mma, cudaFuncAttributeMaxDynamicSharedMemorySize, G2_SMEM);

    conv_x_kernel<<<(MTOT * 1024) / (256 * 8), 256>>>(x);
    build_pp_kernel<<<(1024 * 1024) / 256, 256>>>(core2, core3);
    build_q2_kernel<<<(1024 * 256) / 256, 256>>>(core0, core1);

    gemm1_mma<<<dim3(8, 64), 256, G1_SMEM>>>();
    gemm2_mma<<<dim3(16, 256), 256, G2_SMEM>>>(bias, y);
}

// round 10
// speedup vs baseline: 2.5105x; 1.4482x over previous
#include <cuda_runtime.h>
#include <cuda_fp16.h>
#include <cstdint>

// ---------------------------------------------------------------------------
// TR_Linear via two single-product fp16 GEMMs on the tensor pipe (portable
// PTX: mma.sync.m16n8k16.f16 / ldmatrix / cp.async).
//   Pp^T[n][i'] (1024x1024), n=(r2*16+r4)*4+h ;  C1 = x @ Pp  (K=1024)
//   Q2^T[n2][k] (1024x256),  k=r2*16+r4, n2=i0*32+i1
//   y[b, n2*4+h] = sum_k C1[b,k*4+h]*Q2[k,n2] + bias
// Precision (R10): ALL operands single fp16, fp32 accumulate. Calibrated
// error model (R9: two quantized operands = 2.88e-4) predicts ~4.1e-4 for
// four operands -- 2.4x under the 1e-3 threshold. Halves MMA count again
// (the confirmed throughput wall for legacy HMMA on sm_103a).
// ---------------------------------------------------------------------------

#define MTOT 8192

typedef __half fp16;

__device__ fp16 g_x[MTOT * 1024];
__device__ fp16 g_pp[1024 * 1024];
__device__ fp16 g_q2[1024 * 256];
__device__ fp16 g_c1[4 * MTOT * 256];   // [h][b][k2]

// ========================= PTX helpers (portable) ==========================
__device__ __forceinline__ void cp16(uint32_t dst, const void* src) {
    asm volatile("cp.async.cg.shared.global [%0], [%1], 16;" :: "r"(dst), "l"(src));
}
#define CP_COMMIT() asm volatile("cp.async.commit_group;" ::: "memory")
#define CP_WAIT(N)  asm volatile("cp.async.wait_group %0;" :: "n"(N) : "memory")

__device__ __forceinline__ void ldm4(uint32_t& r0, uint32_t& r1, uint32_t& r2, uint32_t& r3,
                                     uint32_t addr) {
    asm volatile("ldmatrix.sync.aligned.m8n8.x4.shared.b16 {%0,%1,%2,%3}, [%4];"
                 : "=r"(r0), "=r"(r1), "=r"(r2), "=r"(r3) : "r"(addr));
}
__device__ __forceinline__ void mma_fp16(float* d, const uint32_t* a, const uint32_t* b) {
    asm volatile("mma.sync.aligned.m16n8k16.row.col.f32.f16.f16.f32 "
                 "{%0,%1,%2,%3}, {%4,%5,%6,%7}, {%8,%9}, {%0,%1,%2,%3};"
                 : "+f"(d[0]), "+f"(d[1]), "+f"(d[2]), "+f"(d[3])
                 : "r"(a[0]), "r"(a[1]), "r"(a[2]), "r"(a[3]), "r"(b[0]), "r"(b[1]));
}
__device__ __forceinline__ uint32_t cvta_s(const void* p) {
    return (uint32_t)__cvta_generic_to_shared(p);
}

// 64B-row swizzle: row stride = 32 fp16 (64B); 16B granule c (0..3) stored at
// physical granule c ^ ((row>>1)&3). Conflict-free for ldmatrix + cp.async.
__device__ __forceinline__ uint32_t swz(int row, int c) {
    return (uint32_t)(row * 32 + ((c ^ ((row >> 1) & 3)) * 8));
}

// ========================= prepass kernels =================================
__global__ void conv_x_kernel(const float* __restrict__ x) {
    int i = (blockIdx.x * blockDim.x + threadIdx.x) * 8;
    float4 v0 = *(const float4*)(x + i);
    float4 v1 = *(const float4*)(x + i + 4);
    ushort4 h0, h1;
    h0.x = __half_as_ushort(__float2half_rn(v0.x));
    h0.y = __half_as_ushort(__float2half_rn(v0.y));
    h0.z = __half_as_ushort(__float2half_rn(v0.z));
    h0.w = __half_as_ushort(__float2half_rn(v0.w));
    h1.x = __half_as_ushort(__float2half_rn(v1.x));
    h1.y = __half_as_ushort(__float2half_rn(v1.y));
    h1.z = __half_as_ushort(__float2half_rn(v1.z));
    h1.w = __half_as_ushort(__float2half_rn(v1.w));
    *(ushort4*)(g_x + i)     = h0;
    *(ushort4*)(g_x + i + 4) = h1;
}

__global__ void build_pp_kernel(const float* __restrict__ c2, const float* __restrict__ c3) {
    int idx = blockIdx.x * blockDim.x + threadIdx.x;   // n*1024 + i'
    int n = idx >> 10, ip = idx & 1023;
    int r2 = n >> 6, r4 = (n >> 2) & 15, h = n & 3;
    int o0 = h * 16 + (ip >> 6), o1 = ip & 63;
    const float* a = c2 + (r2 * 64 + o0) * 16;
    float s = 0.f;
#pragma unroll
    for (int r3 = 0; r3 < 16; r3++) s += a[r3] * c3[(r3 * 64 + o1) * 16 + r4];
    g_pp[idx] = __float2half_rn(s);
}

__global__ void build_q2_kernel(const float* __restrict__ c0, const float* __restrict__ c1) {
    int idx = blockIdx.x * blockDim.x + threadIdx.x;   // n2*256 + k
    int n2 = idx >> 8, k = idx & 255;
    int r2 = k >> 4, r4 = k & 15;
    int i0 = n2 >> 5, i1 = n2 & 31;
    const float* a = c0 + (r4 * 32 + i0) * 16;
    float s = 0.f;
#pragma unroll
    for (int r1 = 0; r1 < 16; r1++) s += a[r1] * c1[(r1 * 32 + i1) * 16 + r2];
    g_q2[idx] = __float2half_rn(s);
}

// ========================= GEMM1: C1 = x @ Pp ==============================
// 128x128 block tile, 256 threads (8 warps, warp tile 64x32).
// K=1024 in 32 chunks of 32. 4-stage ring, swizzled 64B rows.
// Stage layout (fp16 elems): A[128][32] @0, B[128][32] @4096.
#define G1_SLOT   8192                       // fp16 per stage (16384 B)
#define G1_STAGES 4
#define G1_SMEM   69632                      // max(ring 65536, epilogue 67584)+pad

__global__ __launch_bounds__(256, 2) void gemm1_mma() {
    extern __shared__ char dsm[];
    fp16* sm = (fp16*)dsm;
    const int t = threadIdx.x, wid = t >> 5, lane = t & 31;
    const int bm = blockIdx.y * 128, bn = blockIdx.x * 128;
    const int wm = wid & 1, wn = wid >> 1;     // warp tile 64m x 32n

    float acc[4][4][4];
#pragma unroll
    for (int a = 0; a < 4; a++)
#pragma unroll
        for (int b = 0; b < 4; b++)
#pragma unroll
            for (int c = 0; c < 4; c++) acc[a][b][c] = 0.f;

    auto load_stage = [&](int s, int k0) {
#pragma unroll
        for (int i = 0; i < 4; i++) {
            int gi = i * 256 + t;                      // 1024 x 16B granules
            int arr = gi >> 9, rem = gi & 511, row = rem >> 2, c = rem & 3;
            const fp16* src = arr ? (g_pp + (size_t)(bn + row) * 1024 + k0 + c * 8)
                                  : (g_x  + (size_t)(bm + row) * 1024 + k0 + c * 8);
            cp16(cvta_s(sm + s * G1_SLOT + arr * 4096 + swz(row, c)), src);
        }
    };

    const int lr = lane & 15, lc = lane >> 4;

    auto compute = [&](int s) {
        uint32_t base = cvta_s(sm) + (uint32_t)(s * G1_SLOT) * 2;
#pragma unroll
        for (int kk = 0; kk < 2; kk++) {
            int kidx = kk * 2 + lc;
            uint32_t ah[4][4], bh[4][2];
#pragma unroll
            for (int mi = 0; mi < 4; mi++) {
                int row = wm * 64 + mi * 16 + lr;
                ldm4(ah[mi][0], ah[mi][1], ah[mi][2], ah[mi][3], base + swz(row, kidx) * 2);
            }
#pragma unroll
            for (int p = 0; p < 2; p++) {
                int row = wn * 32 + p * 16 + lr;
                uint32_t r0, r1, r2, r3;
                ldm4(r0, r1, r2, r3, base + 4096 * 2 + swz(row, kidx) * 2);
                bh[2 * p][0] = r0; bh[2 * p][1] = r2;
                bh[2 * p + 1][0] = r1; bh[2 * p + 1][1] = r3;
            }
#pragma unroll
            for (int mi = 0; mi < 4; mi++)
#pragma unroll
                for (int ni = 0; ni < 4; ni++)
                    mma_fp16(acc[mi][ni], ah[mi], bh[ni]);
        }
    };

#pragma unroll
    for (int s = 0; s < G1_STAGES - 1; s++) {
        load_stage(s, s * 32);
        CP_COMMIT();
    }
    for (int kc = 0; kc < 32; kc++) {
        CP_WAIT(2);
        __syncthreads();
        if (kc + 3 < 32) load_stage((kc + 3) % G1_STAGES, (kc + 3) * 32);
        CP_COMMIT();
        compute(kc % G1_STAGES);
    }

    // ---- epilogue: stage fp32 tile, then fp16 into C1[h][b][k2] ----
    CP_WAIT(0);
    __syncthreads();
    float* stg = (float*)dsm;     // [128][132] = 67584 B <= 69632
#pragma unroll
    for (int mi = 0; mi < 4; mi++)
#pragma unroll
        for (int ni = 0; ni < 4; ni++) {
            int r = wm * 64 + mi * 16 + (lane >> 2);
            int c = wn * 32 + ni * 8 + (lane & 3) * 2;
            stg[r * 132 + c]           = acc[mi][ni][0];
            stg[r * 132 + c + 1]       = acc[mi][ni][1];
            stg[(r + 8) * 132 + c]     = acc[mi][ni][2];
            stg[(r + 8) * 132 + c + 1] = acc[mi][ni][3];
        }
    __syncthreads();

    const int kb = bn >> 2;
#pragma unroll
    for (int i = 0; i < 16; i++) {
        int g = i * 256 + t;                   // 4096 groups of 4 k2
        int row = g >> 5, rem = g & 31, h = rem >> 3, kg = rem & 7;
        ushort4 vh;
        vh.x = __half_as_ushort(__float2half_rn(stg[row * 132 + (kg * 4 + 0) * 4 + h]));
        vh.y = __half_as_ushort(__float2half_rn(stg[row * 132 + (kg * 4 + 1) * 4 + h]));
        vh.z = __half_as_ushort(__float2half_rn(stg[row * 132 + (kg * 4 + 2) * 4 + h]));
        vh.w = __half_as_ushort(__float2half_rn(stg[row * 132 + (kg * 4 + 3) * 4 + h]));
        size_t o = ((size_t)h * MTOT + bm + row) * 256 + kb + kg * 4;
        *(ushort4*)(g_c1 + o) = vh;
    }
}

// ========================= GEMM2: y = C1_h @ Q2^T + bias ===================
// 256 threads, block 64b x 64n2 x 4h. Warp: h = wid>>1, rows (wid&1)*32..+31.
// K=256 in 8 chunks of 32. Q2 RESIDENT full-K (8 chunked [64][32] tiles);
// A (4h x 64 x 32) in 3-stage ring, 1 sync/chunk.
#define G2_SLOT  8192                       // fp16 per A stage (16384 B)
#define G2_B     (3 * G2_SLOT)              // 24576 fp16 offset
#define G2_SMEM  ((G2_B + 8 * 2048) * 2)    // 81920 B

__global__ __launch_bounds__(256, 2) void gemm2_mma(const float* __restrict__ bias,
                                                    float* __restrict__ Y) {
    extern __shared__ char dsm[];
    fp16* sm = (fp16*)dsm;
    const int t = threadIdx.x, wid = t >> 5, lane = t & 31;
    const int bm = blockIdx.y * 64, bn2 = blockIdx.x * 64;
    const int wh = wid >> 1, mh = wid & 1;     // warp: h = wh, rows mh*32..+31

    float acc[2][8][4];
#pragma unroll
    for (int a = 0; a < 2; a++)
#pragma unroll
        for (int b = 0; b < 8; b++)
#pragma unroll
            for (int c = 0; c < 4; c++) acc[a][b][c] = 0.f;

    auto load_B = [&]() {        // full-K Q2, chunked [kc][64][32]
#pragma unroll
        for (int i = 0; i < 8; i++) {
            int gi = i * 256 + t;                    // 2048 x 16B granules
            int kcch = gi >> 8, rem = gi & 255, row = rem >> 2, c = rem & 3;
            const fp16* src = g_q2 + (size_t)(bn2 + row) * 256 + kcch * 32 + c * 8;
            cp16(cvta_s(sm + G2_B + kcch * 2048 + swz(row, c)), src);
        }
    };
    auto load_stage = [&](int s, int k0) {
#pragma unroll
        for (int i = 0; i < 4; i++) {
            int gi = i * 256 + t;                    // 1024 x 16B granules
            int h = gi >> 8, rem = gi & 255, row = rem >> 2, c = rem & 3;
            const fp16* src = g_c1 + ((size_t)h * MTOT + bm + row) * 256 + k0 + c * 8;
            cp16(cvta_s(sm + s * G2_SLOT + h * 2048 + swz(row, c)), src);
        }
    };

    const int lr = lane & 15, lc = lane >> 4;

    auto compute = [&](int s, int kc) {
        uint32_t abase = cvta_s(sm) + (uint32_t)(s * G2_SLOT) * 2;
        uint32_t bbase = cvta_s(sm) + (uint32_t)(G2_B + kc * 2048) * 2;
#pragma unroll
        for (int kk = 0; kk < 2; kk++) {
            int kidx = kk * 2 + lc;
            uint32_t ah[2][4], bh[8][2];
#pragma unroll
            for (int mi = 0; mi < 2; mi++) {
                int row = mh * 32 + mi * 16 + lr;
                ldm4(ah[mi][0], ah[mi][1], ah[mi][2], ah[mi][3],
                     abase + ((uint32_t)(wh * 2048) + swz(row, kidx)) * 2);
            }
#pragma unroll
            for (int p = 0; p < 4; p++) {
                int row = p * 16 + lr;
                uint32_t r0, r1, r2, r3;
                ldm4(r0, r1, r2, r3, bbase + swz(row, kidx) * 2);
                bh[2 * p][0] = r0; bh[2 * p][1] = r2;
                bh[2 * p + 1][0] = r1; bh[2 * p + 1][1] = r3;
            }
#pragma unroll
            for (int mi = 0; mi < 2; mi++)
#pragma unroll
                for (int ni = 0; ni < 8; ni++)
                    mma_fp16(acc[mi][ni], ah[mi], bh[ni]);
        }
    };

    load_B();
    load_stage(0, 0);
    CP_COMMIT();                 // group 0: B + stage0
    load_stage(1, 32);
    CP_COMMIT();                 // group 1: stage1
    for (int kc = 0; kc < 8; kc++) {
        CP_WAIT(1);
        __syncthreads();
        if (kc + 2 < 8) load_stage((kc + 2) % 3, (kc + 2) * 32);
        CP_COMMIT();
        compute(kc % 3, kc);
    }

    // ---- epilogue: reorder (h, n2l) -> col n2l*4+h in smem, coalesced out ----
    CP_WAIT(0);
    __syncthreads();
    float* stg = (float*)dsm;     // [64][260] = 66560 B <= 81920
#pragma unroll
    for (int mi = 0; mi < 2; mi++)
#pragma unroll
        for (int ni = 0; ni < 8; ni++) {
            int r = mh * 32 + mi * 16 + (lane >> 2);
            int n2l = ni * 8 + (lane & 3) * 2;
            stg[r * 260 + n2l * 4 + wh]             = acc[mi][ni][0];
            stg[r * 260 + (n2l + 1) * 4 + wh]       = acc[mi][ni][1];
            stg[(r + 8) * 260 + n2l * 4 + wh]       = acc[mi][ni][2];
            stg[(r + 8) * 260 + (n2l + 1) * 4 + wh] = acc[mi][ni][3];
        }
    __syncthreads();

#pragma unroll
    for (int i = 0; i < 16; i++) {
        int g = i * 256 + t;                    // 4096 float4 groups
        int r = g >> 6, c4 = (g & 63) * 4;
        float4 v = *(const float4*)&stg[r * 260 + c4];
        float4 bz = *(const float4*)(bias + bn2 * 4 + c4);
        v.x += bz.x; v.y += bz.y; v.z += bz.z; v.w += bz.w;
        *(float4*)(Y + (size_t)(bm + r) * 4096 + bn2 * 4 + c4) = v;
    }
}

// ========================= launch ==========================================
extern "C" void kernel_launch(void* const* d_in, const int* in_sizes, int n_in,
                              void* d_out, int out_size) {
    const float* x     = (const float*)d_in[0];
    const float* core0 = (const float*)d_in[1];
    const float* core1 = (const float*)d_in[2];
    const float* core2 = (const float*)d_in[3];
    const float* core3 = (const float*)d_in[4];
    const float* bias  = (const float*)d_in[5];
    float* y = (float*)d_out;

    cudaFuncSetAttribute(gemm1_mma, cudaFuncAttributeMaxDynamicSharedMemorySize, G1_SMEM);
    cudaFuncSetAttribute(gemm2_mma, cudaFuncAttributeMaxDynamicSharedMemorySize, G2_SMEM);

    conv_x_kernel<<<(MTOT * 1024) / (256 * 8), 256>>>(x);
    build_pp_kernel<<<(1024 * 1024) / 256, 256>>>(core2, core3);
    build_q2_kernel<<<(1024 * 256) / 256, 256>>>(core0, core1);

    gemm1_mma<<<dim3(8, 64), 256, G1_SMEM>>>();
    gemm2_mma<<<dim3(16, 128), 256, G2_SMEM>>>(bias, y);
}